// round 1
// baseline (speedup 1.0000x reference)
#include <cuda_runtime.h>

// Problem constants
#define BB 4
#define CC 64
#define NN 4096
#define C8V 8
#define NIMG 8          // 4 cnn images + 4 vit images
#define NCHUNK 32       // gram / applyA chunks of 128 columns
#define KSPLIT 4
#define KTILE 64

// ---------------- scratch (static device globals; no allocation) -----------
__device__ float g_gpart[NCHUNK * NIMG * CC * CC];   // per-chunk gram partials
__device__ float g_A[NIMG * CC * CC];                // channel-attention matrices
__device__ float g_ycnn[BB * CC * NN];               // cl_attention(cnn)
__device__ float g_yvit[BB * CC * NN];               // cl_attention(vit)
__device__ float g_q[BB * NN * C8V];
__device__ float g_k[BB * NN * C8V];
__device__ float g_v[BB * NN * CC];
__device__ float g_pout[BB * KSPLIT * CC * NN];      // flash partial outputs [bs][c][q]
__device__ float g_pml[BB * KSPLIT * NN * 2];        // flash partial (m,l)

// ---------------- Stage A1: gram partials G = xf . xf^T ---------------------
__global__ void k_gram(const float* __restrict__ cnn, const float* __restrict__ vit) {
    int chunk = blockIdx.x, img = blockIdx.y;
    const float* x = (img < BB) ? (cnn + img * CC * NN) : (vit + (img - BB) * CC * NN);
    __shared__ float xs[CC][129];                    // pad: conflict-free xs[cj][j]
    int n0 = chunk * 128;
    for (int i = threadIdx.x; i < CC * 128; i += 256) {
        int c = i >> 7, j = i & 127;
        xs[c][j] = x[c * NN + n0 + j];
    }
    __syncthreads();
    float* outp = g_gpart + (chunk * NIMG + img) * CC * CC;
    for (int p = threadIdx.x; p < CC * CC; p += 256) {
        int ci = p >> 6, cj = p & 63;
        float s = 0.f;
        #pragma unroll 8
        for (int j = 0; j < 128; j++) s += xs[ci][j] * xs[cj][j];
        outp[p] = s;
    }
}

// ---------------- Stage A2: reduce partials + A = softmax(-G) ---------------
__global__ void k_softmaxA() {
    int img = blockIdx.x;
    __shared__ float Gs[CC * CC];
    for (int p = threadIdx.x; p < CC * CC; p += 256) {
        float s = 0.f;
        #pragma unroll
        for (int ch = 0; ch < NCHUNK; ch++)
            s += g_gpart[(ch * NIMG + img) * CC * CC + p];
        Gs[p] = s;
    }
    __syncthreads();
    if (threadIdx.x < CC) {
        int r = threadIdx.x;
        float m = -1e30f;
        for (int d = 0; d < CC; d++) m = fmaxf(m, -Gs[r * CC + d]);
        float sum = 0.f;
        for (int d = 0; d < CC; d++) sum += __expf(-Gs[r * CC + d] - m);
        float inv = 1.f / sum;
        for (int d = 0; d < CC; d++)
            g_A[img * CC * CC + r * CC + d] = __expf(-Gs[r * CC + d] - m) * inv;
    }
}

// ---------------- Stage A3: y = gamma_cla * (A @ x) + x ---------------------
__global__ void k_applyA(const float* __restrict__ cnn, const float* __restrict__ vit,
                         const float* __restrict__ gcnn, const float* __restrict__ gvit) {
    int chunk = blockIdx.x, img = blockIdx.y;
    const float* x; float* y; float g;
    if (img < BB) { x = cnn + img * CC * NN; y = g_ycnn + img * CC * NN; g = gcnn[0]; }
    else          { x = vit + (img - BB) * CC * NN; y = g_yvit + (img - BB) * CC * NN; g = gvit[0]; }
    __shared__ float As[CC * CC];
    __shared__ float xs[CC][128];                    // reads are lane-consecutive in n: no pad needed
    int n0 = chunk * 128;
    for (int i = threadIdx.x; i < CC * 128; i += 256) {
        int c = i >> 7, j = i & 127;
        xs[c][j] = x[c * NN + n0 + j];
    }
    for (int p = threadIdx.x; p < CC * CC; p += 256) As[p] = g_A[img * CC * CC + p];
    __syncthreads();
    int n = threadIdx.x & 127;
    int ch0 = (threadIdx.x >> 7) * 32;
    float acc[32];
    #pragma unroll
    for (int i = 0; i < 32; i++) acc[i] = 0.f;
    for (int d = 0; d < CC; d++) {
        float xv = xs[d][n];
        #pragma unroll
        for (int i = 0; i < 32; i++) acc[i] += As[(ch0 + i) * CC + d] * xv;
    }
    #pragma unroll
    for (int i = 0; i < 32; i++)
        y[(ch0 + i) * NN + n0 + n] = g * acc[i] + xs[ch0 + i][n];
}

// ---------------- Stage B1: q, k projections (C8=8 each) --------------------
__global__ void k_qk(const float* __restrict__ Wq, const float* __restrict__ bq,
                     const float* __restrict__ Wk, const float* __restrict__ bk) {
    int n0 = blockIdx.x * 64; int b = blockIdx.y;
    __shared__ float cs[CC][64], vs[CC][64];
    __shared__ float Wqs[C8V][CC], Wks[C8V][CC];
    const float* yc = g_ycnn + b * CC * NN;
    const float* yv = g_yvit + b * CC * NN;
    for (int i = threadIdx.x; i < CC * 64; i += 128) {
        int c = i >> 6, j = i & 63;
        cs[c][j] = yc[c * NN + n0 + j];
        vs[c][j] = yv[c * NN + n0 + j];
    }
    for (int i = threadIdx.x; i < C8V * CC; i += 128) {
        Wqs[i >> 6][i & 63] = Wq[i];
        Wks[i >> 6][i & 63] = Wk[i];
    }
    __syncthreads();
    int n = threadIdx.x & 63;
    bool doQ = threadIdx.x < 64;
    const float* bias = doQ ? bq : bk;
    float acc[8];
    #pragma unroll
    for (int o = 0; o < 8; o++) acc[o] = bias[o];
    if (doQ) {
        for (int c = 0; c < CC; c++) {
            float xv = cs[c][n];
            #pragma unroll
            for (int o = 0; o < 8; o++) acc[o] += Wqs[o][c] * xv;
        }
        float* dst = g_q + (b * NN + n0 + n) * C8V;
        #pragma unroll
        for (int o = 0; o < 8; o++) dst[o] = acc[o];
    } else {
        for (int c = 0; c < CC; c++) {
            float xv = vs[c][n];
            #pragma unroll
            for (int o = 0; o < 8; o++) acc[o] += Wks[o][c] * xv;
        }
        float* dst = g_k + (b * NN + n0 + n) * C8V;
        #pragma unroll
        for (int o = 0; o < 8; o++) dst[o] = acc[o];
    }
}

// ---------------- Stage B2: v projection (C=64) ------------------------------
__global__ void k_vproj(const float* __restrict__ Wv, const float* __restrict__ bv) {
    int n0 = blockIdx.x * 64; int b = blockIdx.y;
    __shared__ float vs[CC][64];
    __shared__ float Ws[CC][CC];                     // Ws[cprime][c]
    const float* yv = g_yvit + b * CC * NN;
    for (int i = threadIdx.x; i < CC * 64; i += 256)
        vs[i >> 6][i & 63] = yv[(i >> 6) * NN + n0 + (i & 63)];
    for (int i = threadIdx.x; i < CC * CC; i += 256)
        Ws[i >> 6][i & 63] = Wv[i];
    __syncthreads();
    int n = threadIdx.x & 63;
    int cp0 = (threadIdx.x >> 6) * 16;
    float acc[16];
    #pragma unroll
    for (int i = 0; i < 16; i++) acc[i] = bv[cp0 + i];
    for (int c = 0; c < CC; c++) {
        float xv = vs[c][n];
        #pragma unroll
        for (int i = 0; i < 16; i++) acc[i] += Ws[cp0 + i][c] * xv;
    }
    float* dst = g_v + (b * NN + n0 + n) * CC + cp0;
    #pragma unroll
    for (int i = 0; i < 16; i++) dst[i] = acc[i];
}

// ---------------- Stage C: flash attention, split-K partials -----------------
__global__ void __launch_bounds__(256, 2) k_flash() {
    int split = blockIdx.x, qt = blockIdx.y, b = blockIdx.z;
    int q = qt * 256 + threadIdx.x;
    const float* qp = g_q + (b * NN + q) * C8V;
    float4 qa = *(const float4*)qp;
    float4 qb = *(const float4*)(qp + 4);
    float qr[8] = {qa.x, qa.y, qa.z, qa.w, qb.x, qb.y, qb.z, qb.w};

    __shared__ float ks[KTILE][8];
    __shared__ float vs[KTILE][64];

    float m = -1e30f, l = 0.f;
    unsigned long long acc[32];                      // 64 fp32 accumulators, packed
    #pragma unroll
    for (int i = 0; i < 32; i++) acc[i] = 0ull;

    int kbase = split * (NN / KSPLIT);
    for (int t = 0; t < (NN / KSPLIT) / KTILE; t++) {
        int k0 = kbase + t * KTILE;
        __syncthreads();
        for (int i = threadIdx.x; i < KTILE * 2; i += 256) {
            int row = i >> 1, half = i & 1;
            *(float4*)&ks[row][half * 4] = *(const float4*)(g_k + (b * NN + k0 + row) * C8V + half * 4);
        }
        for (int i = threadIdx.x; i < KTILE * 16; i += 256) {
            int row = i >> 4, c4 = i & 15;
            *(float4*)&vs[row][c4 * 4] = *(const float4*)(g_v + (b * NN + k0 + row) * CC + c4 * 4);
        }
        __syncthreads();
        for (int j = 0; j < KTILE; j++) {
            float e = 0.f;
            #pragma unroll
            for (int i = 0; i < 8; i++) e += qr[i] * ks[j][i];
            float p;
            if (e > m) {                              // rare (energies are tiny)
                float sc = __expf(m - e);
                l *= sc;
                unsigned long long sc2;
                asm("mov.b64 %0, {%1,%1};" : "=l"(sc2) : "f"(sc));
                #pragma unroll
                for (int i = 0; i < 32; i++)
                    asm("mul.rn.f32x2 %0, %0, %1;" : "+l"(acc[i]) : "l"(sc2));
                m = e; p = 1.f;
            } else {
                p = __expf(e - m);
            }
            l += p;
            unsigned long long p2;
            asm("mov.b64 %0, {%1,%1};" : "=l"(p2) : "f"(p));
            const unsigned long long* vrow = (const unsigned long long*)&vs[j][0];
            #pragma unroll
            for (int i = 0; i < 32; i++)
                asm("fma.rn.f32x2 %0, %1, %2, %0;" : "+l"(acc[i]) : "l"(p2), "l"(vrow[i]));
        }
    }

    int bs = b * KSPLIT + split;
    *(float2*)(g_pml + (bs * NN + q) * 2) = make_float2(m, l);
    float* po = g_pout + bs * CC * NN + q;            // [bs][c][q] -> coalesced in q
    #pragma unroll
    for (int i = 0; i < 32; i++) {
        float lo, hi;
        asm("mov.b64 {%0,%1}, %2;" : "=f"(lo), "=f"(hi) : "l"(acc[i]));
        po[(2 * i) * NN]     = lo;
        po[(2 * i + 1) * NN] = hi;
    }
}

// ---------------- Stage D: combine splits + epilogue -------------------------
__global__ void k_combine(const float* __restrict__ gamma, const float* __restrict__ cnn,
                          float* __restrict__ out) {
    int b = blockIdx.y;
    int q = blockIdx.x * 128 + (threadIdx.x & 127);
    int c0 = (threadIdx.x >> 7) * 32;
    float mm[KSPLIT], ll[KSPLIT];
    float M = -1e30f;
    #pragma unroll
    for (int s = 0; s < KSPLIT; s++) {
        float2 ml = *(const float2*)(g_pml + ((b * KSPLIT + s) * NN + q) * 2);
        mm[s] = ml.x; ll[s] = ml.y;
        M = fmaxf(M, ml.x);
    }
    float w[KSPLIT]; float L = 0.f;
    #pragma unroll
    for (int s = 0; s < KSPLIT; s++) { w[s] = __expf(mm[s] - M); L += ll[s] * w[s]; }
    float inv = 1.f / L;
    #pragma unroll
    for (int s = 0; s < KSPLIT; s++) w[s] *= inv;
    float g = gamma[0];
    for (int i = 0; i < 32; i++) {
        int c = c0 + i;
        float o = 0.f;
        #pragma unroll
        for (int s = 0; s < KSPLIT; s++)
            o += g_pout[((b * KSPLIT + s) * CC + c) * NN + q] * w[s];
        out[(b * CC + c) * NN + q] = g * o + cnn[(b * CC + c) * NN + q];
    }
}

// ---------------- launch ------------------------------------------------------
extern "C" void kernel_launch(void* const* d_in, const int* in_sizes, int n_in,
                              void* d_out, int out_size) {
    const float* cnn   = (const float*)d_in[0];
    const float* vit   = (const float*)d_in[1];
    const float* Wq    = (const float*)d_in[2];
    const float* bq    = (const float*)d_in[3];
    const float* Wk    = (const float*)d_in[4];
    const float* bk    = (const float*)d_in[5];
    const float* Wv    = (const float*)d_in[6];
    const float* bv    = (const float*)d_in[7];
    const float* gamma = (const float*)d_in[8];
    const float* gcnn  = (const float*)d_in[9];
    const float* gvit  = (const float*)d_in[10];
    float* out = (float*)d_out;

    k_gram    <<<dim3(NCHUNK, NIMG), 256>>>(cnn, vit);
    k_softmaxA<<<NIMG, 256>>>();
    k_applyA  <<<dim3(NCHUNK, NIMG), 256>>>(cnn, vit, gcnn, gvit);
    k_qk      <<<dim3(NN / 64, BB), 128>>>(Wq, bq, Wk, bk);
    k_vproj   <<<dim3(NN / 64, BB), 256>>>(Wv, bv);
    k_flash   <<<dim3(KSPLIT, NN / 256, BB), 256>>>();
    k_combine <<<dim3(NN / 128, BB), 256>>>(gamma, cnn, out);
}

// round 3
// speedup vs baseline: 2.7453x; 2.7453x over previous
#include <cuda_runtime.h>
#include <cuda_bf16.h>
#include <cstdint>

// Problem constants
#define BB 4
#define CC 64
#define NN 4096
#define C8V 8
#define NIMG 8
#define NCHUNK 32

// ---------------- scratch ----------------------------------------------------
__device__ float g_gpart[NCHUNK * NIMG * CC * CC];
__device__ float g_A[NIMG * CC * CC];
__device__ float g_ycnn[BB * CC * NN];
__device__ float g_yvit[BB * CC * NN];
__device__ __nv_bfloat16 g_qb[BB * NN * C8V];      // [b][n][8]  (prescaled by 1/ln2)
__device__ __nv_bfloat16 g_kb[BB * NN * C8V];      // [b][n][8]
__device__ __nv_bfloat16 g_v [BB * NN * CC];       // [b][n][c]  (key-major)

__device__ __forceinline__ uint32_t smem_u32(const void* p) {
    uint32_t a;
    asm("{ .reg .u64 t; cvta.to.shared.u64 t, %1; cvt.u32.u64 %0, t; }" : "=r"(a) : "l"(p));
    return a;
}

// mma.sync m16n8k16 bf16, fp32 accum (D == C, accumulate in place)
#define MMA_BF16(d, a0, a1, a2, a3, b0, b1)                                        \
    asm volatile("mma.sync.aligned.m16n8k16.row.col.f32.bf16.bf16.f32 "            \
        "{%0,%1,%2,%3}, {%4,%5,%6,%7}, {%8,%9}, {%0,%1,%2,%3};"                    \
        : "+f"((d)[0]), "+f"((d)[1]), "+f"((d)[2]), "+f"((d)[3])                   \
        : "r"(a0), "r"(a1), "r"(a2), "r"(a3), "r"(b0), "r"(b1))

// ---------------- Stage A1: gram partials ------------------------------------
__global__ void k_gram(const float* __restrict__ cnn, const float* __restrict__ vit) {
    int chunk = blockIdx.x, img = blockIdx.y;
    const float* x = (img < BB) ? (cnn + img * CC * NN) : (vit + (img - BB) * CC * NN);
    __shared__ float xs[CC][129];
    int n0 = chunk * 128;
    for (int i = threadIdx.x; i < CC * 128; i += 256) {
        int c = i >> 7, j = i & 127;
        xs[c][j] = x[c * NN + n0 + j];
    }
    __syncthreads();
    float* outp = g_gpart + (chunk * NIMG + img) * CC * CC;
    for (int p = threadIdx.x; p < CC * CC; p += 256) {
        int ci = p >> 6, cj = p & 63;
        float s = 0.f;
        #pragma unroll 8
        for (int j = 0; j < 128; j++) s += xs[ci][j] * xs[cj][j];
        outp[p] = s;
    }
}

// ---------------- Stage A2: A = softmax(-G) ----------------------------------
__global__ void k_softmaxA() {
    int img = blockIdx.x;
    __shared__ float Gs[CC * CC];
    for (int p = threadIdx.x; p < CC * CC; p += 256) {
        float s = 0.f;
        #pragma unroll
        for (int ch = 0; ch < NCHUNK; ch++)
            s += g_gpart[(ch * NIMG + img) * CC * CC + p];
        Gs[p] = s;
    }
    __syncthreads();
    if (threadIdx.x < CC) {
        int r = threadIdx.x;
        float m = -1e30f;
        for (int d = 0; d < CC; d++) m = fmaxf(m, -Gs[r * CC + d]);
        float sum = 0.f;
        for (int d = 0; d < CC; d++) sum += __expf(-Gs[r * CC + d] - m);
        float inv = 1.f / sum;
        for (int d = 0; d < CC; d++)
            g_A[img * CC * CC + r * CC + d] = __expf(-Gs[r * CC + d] - m) * inv;
    }
}

// ---------------- Stage A3: y = gamma_cla*(A@x)+x -----------------------------
__global__ void k_applyA(const float* __restrict__ cnn, const float* __restrict__ vit,
                         const float* __restrict__ gcnn, const float* __restrict__ gvit) {
    int chunk = blockIdx.x, img = blockIdx.y;
    const float* x; float* y; float g;
    if (img < BB) { x = cnn + img * CC * NN; y = g_ycnn + img * CC * NN; g = gcnn[0]; }
    else          { x = vit + (img - BB) * CC * NN; y = g_yvit + (img - BB) * CC * NN; g = gvit[0]; }
    __shared__ float As[CC * CC];
    __shared__ float xs[CC][128];
    int n0 = chunk * 128;
    for (int i = threadIdx.x; i < CC * 128; i += 256) {
        int c = i >> 7, j = i & 127;
        xs[c][j] = x[c * NN + n0 + j];
    }
    for (int p = threadIdx.x; p < CC * CC; p += 256) As[p] = g_A[img * CC * CC + p];
    __syncthreads();
    int n = threadIdx.x & 127;
    int ch0 = (threadIdx.x >> 7) * 32;
    float acc[32];
    #pragma unroll
    for (int i = 0; i < 32; i++) acc[i] = 0.f;
    for (int d = 0; d < CC; d++) {
        float xv = xs[d][n];
        #pragma unroll
        for (int i = 0; i < 32; i++) acc[i] += As[(ch0 + i) * CC + d] * xv;
    }
    #pragma unroll
    for (int i = 0; i < 32; i++)
        y[(ch0 + i) * NN + n0 + n] = g * acc[i] + xs[ch0 + i][n];
}

// ---------------- Stage B1: q / k projections -> bf16 -------------------------
// q is prescaled by 1/ln2 so attention softmax can use ex2 directly.
__global__ void k_qk(const float* __restrict__ Wq, const float* __restrict__ bq,
                     const float* __restrict__ Wk, const float* __restrict__ bk) {
    int n0 = blockIdx.x * 128, b = blockIdx.y, z = blockIdx.z;
    const float* src = (z == 0) ? (g_ycnn + b * CC * NN) : (g_yvit + b * CC * NN);
    const float* W = (z == 0) ? Wq : Wk;
    const float* bias = (z == 0) ? bq : bk;
    __nv_bfloat16* dst = (z == 0) ? g_qb : g_kb;
    float postscale = (z == 0) ? 1.4426950408889634f : 1.0f;
    __shared__ float xs[CC][128];
    __shared__ float Ws[C8V][CC];
    for (int i = threadIdx.x; i < CC * 128; i += 256) {
        int c = i >> 7, j = i & 127;
        xs[c][j] = src[c * NN + n0 + j];
    }
    for (int i = threadIdx.x; i < C8V * CC; i += 256) Ws[i >> 6][i & 63] = W[i];
    __syncthreads();
    int n = threadIdx.x & 127;
    int og = (threadIdx.x >> 7) * 4;
    float acc[4];
    #pragma unroll
    for (int o = 0; o < 4; o++) acc[o] = bias[og + o];
    for (int c = 0; c < CC; c++) {
        float xv = xs[c][n];
        #pragma unroll
        for (int o = 0; o < 4; o++) acc[o] += Ws[og + o][c] * xv;
    }
    ushort4 u;
    u.x = __bfloat16_as_ushort(__float2bfloat16(acc[0] * postscale));
    u.y = __bfloat16_as_ushort(__float2bfloat16(acc[1] * postscale));
    u.z = __bfloat16_as_ushort(__float2bfloat16(acc[2] * postscale));
    u.w = __bfloat16_as_ushort(__float2bfloat16(acc[3] * postscale));
    *(ushort4*)(dst + ((size_t)(b * NN + n0 + n)) * 8 + og) = u;
}

// ---------------- Stage B2: v projection -> bf16 [b][n][c] --------------------
__global__ void k_vproj(const float* __restrict__ Wv, const float* __restrict__ bv) {
    int n0 = blockIdx.x * 64, b = blockIdx.y;
    __shared__ float vs[CC][64];
    __shared__ float Ws[CC][CC];
    const float* yv = g_yvit + b * CC * NN;
    for (int i = threadIdx.x; i < CC * 64; i += 256)
        vs[i >> 6][i & 63] = yv[(i >> 6) * NN + n0 + (i & 63)];
    for (int i = threadIdx.x; i < CC * CC; i += 256)
        Ws[i >> 6][i & 63] = Wv[i];
    __syncthreads();
    int n = threadIdx.x & 63;
    int cp0 = (threadIdx.x >> 6) * 16;
    float acc[16];
    #pragma unroll
    for (int i = 0; i < 16; i++) acc[i] = bv[cp0 + i];
    for (int c = 0; c < CC; c++) {
        float xv = vs[c][n];
        #pragma unroll
        for (int i = 0; i < 16; i++) acc[i] += Ws[cp0 + i][c] * xv;
    }
    ushort4 u0, u1;
    u0.x = __bfloat16_as_ushort(__float2bfloat16(acc[0]));
    u0.y = __bfloat16_as_ushort(__float2bfloat16(acc[1]));
    u0.z = __bfloat16_as_ushort(__float2bfloat16(acc[2]));
    u0.w = __bfloat16_as_ushort(__float2bfloat16(acc[3]));
    u1.x = __bfloat16_as_ushort(__float2bfloat16(acc[4]));
    u1.y = __bfloat16_as_ushort(__float2bfloat16(acc[5]));
    u1.z = __bfloat16_as_ushort(__float2bfloat16(acc[6]));
    u1.w = __bfloat16_as_ushort(__float2bfloat16(acc[7]));
    __nv_bfloat16* dst = g_v + ((size_t)(b * NN + n0 + n)) * CC + cp0;
    *(ushort4*)(dst + 0) = u0;
    *(ushort4*)(dst + 4) = u1;
    ushort4 u2, u3;
    u2.x = __bfloat16_as_ushort(__float2bfloat16(acc[8]));
    u2.y = __bfloat16_as_ushort(__float2bfloat16(acc[9]));
    u2.z = __bfloat16_as_ushort(__float2bfloat16(acc[10]));
    u2.w = __bfloat16_as_ushort(__float2bfloat16(acc[11]));
    u3.x = __bfloat16_as_ushort(__float2bfloat16(acc[12]));
    u3.y = __bfloat16_as_ushort(__float2bfloat16(acc[13]));
    u3.z = __bfloat16_as_ushort(__float2bfloat16(acc[14]));
    u3.w = __bfloat16_as_ushort(__float2bfloat16(acc[15]));
    *(ushort4*)(dst + 8) = u2;
    *(ushort4*)(dst + 12) = u3;
}

// ---------------- Stage C: mma.sync attention ---------------------------------
// grid (32, 4), 128 threads (4 warps). Each warp owns 32 query rows.
__global__ void __launch_bounds__(128) k_attn(const float* __restrict__ gamma,
                                              const float* __restrict__ cnn,
                                              float* __restrict__ out) {
    int qt = blockIdx.x, b = blockIdx.y;
    int tid = threadIdx.x;
    int w = tid >> 5, lane = tid & 31;
    int g = lane >> 2, tp = lane & 3;

    __shared__ __align__(16) __nv_bfloat16 Ks[128][8];     // [key][d]
    __shared__ __align__(16) __nv_bfloat16 Vs[128][72];    // [key][ch], padded

    // Q A-fragments (k = 8 real dims; a2/a3 = 0)
    int qbase = qt * 128 + w * 32;
    uint32_t qa[2][2];
    #pragma unroll
    for (int i = 0; i < 2; i++) {
        qa[i][0] = *(const uint32_t*)(g_qb + ((size_t)(b * NN + qbase + i * 16 + g)) * 8 + 2 * tp);
        qa[i][1] = *(const uint32_t*)(g_qb + ((size_t)(b * NN + qbase + i * 16 + g + 8)) * 8 + 2 * tp);
    }

    float d2[2][8][4];
    #pragma unroll
    for (int i = 0; i < 2; i++)
        #pragma unroll
        for (int j = 0; j < 8; j++)
            #pragma unroll
            for (int r = 0; r < 4; r++) d2[i][j][r] = 0.f;
    float lrow[4] = {0.f, 0.f, 0.f, 0.f};

    for (int t = 0; t < 32; t++) {
        __syncthreads();
        // K tile: 128 keys x 16B
        *(uint4*)&Ks[tid][0] = *(const uint4*)(g_kb + ((size_t)(b * NN + t * 128 + tid)) * 8);
        // V tile: 128 keys x 64 ch (coalesced 512B runs)
        #pragma unroll
        for (int i = 0; i < 8; i++) {
            int idx = tid + i * 128;
            int key = idx >> 3, c8 = (idx & 7) * 8;
            *(uint4*)&Vs[key][c8] = *(const uint4*)(g_v + ((size_t)(b * NN + t * 128 + key)) * CC + c8);
        }
        __syncthreads();

        for (int kc = 0; kc < 8; kc++) {
            // K B-fragments: two n8 blocks (keys kc*16 .. +15)
            uint32_t kb0, kb1;
            {
                uint32_t addr = smem_u32(&Ks[kc * 16 + (lane & 15)][0]);
                asm volatile("ldmatrix.sync.aligned.m8n8.x2.shared.b16 {%0,%1}, [%2];"
                             : "=r"(kb0), "=r"(kb1) : "r"(addr));
            }
            // V B-fragments: 8 n8 blocks (64 ch), k16 = this key chunk
            uint32_t vb[8][2];
            #pragma unroll
            for (int m = 0; m < 4; m++) {
                uint32_t addr = smem_u32(&Vs[kc * 16 + (lane & 15)][(lane >> 4) * 8 + m * 16]);
                asm volatile("ldmatrix.sync.aligned.m8n8.x4.trans.shared.b16 {%0,%1,%2,%3}, [%4];"
                             : "=r"(vb[2 * m][0]), "=r"(vb[2 * m][1]),
                               "=r"(vb[2 * m + 1][0]), "=r"(vb[2 * m + 1][1])
                             : "r"(addr));
            }
            #pragma unroll
            for (int i = 0; i < 2; i++) {
                // S = Q K^T (two n8 key blocks)
                float s0[4] = {0.f, 0.f, 0.f, 0.f}, s1[4] = {0.f, 0.f, 0.f, 0.f};
                MMA_BF16(s0, qa[i][0], qa[i][1], 0u, 0u, kb0, 0u);
                MMA_BF16(s1, qa[i][0], qa[i][1], 0u, 0u, kb1, 0u);
                // P = 2^S (q prescaled by 1/ln2)
                float p0[4], p1[4];
                #pragma unroll
                for (int r = 0; r < 4; r++) {
                    asm("ex2.approx.f32 %0, %1;" : "=f"(p0[r]) : "f"(s0[r]));
                    asm("ex2.approx.f32 %0, %1;" : "=f"(p1[r]) : "f"(s1[r]));
                }
                lrow[2 * i]     += p0[0] + p0[1] + p1[0] + p1[1];
                lrow[2 * i + 1] += p0[2] + p0[3] + p1[2] + p1[3];
                // pack P into A-fragment (C-frag -> A-frag identity)
                uint32_t pa0, pa1, pa2, pa3;
                asm("cvt.rn.bf16x2.f32 %0, %1, %2;" : "=r"(pa0) : "f"(p0[1]), "f"(p0[0]));
                asm("cvt.rn.bf16x2.f32 %0, %1, %2;" : "=r"(pa1) : "f"(p0[3]), "f"(p0[2]));
                asm("cvt.rn.bf16x2.f32 %0, %1, %2;" : "=r"(pa2) : "f"(p1[1]), "f"(p1[0]));
                asm("cvt.rn.bf16x2.f32 %0, %1, %2;" : "=r"(pa3) : "f"(p1[3]), "f"(p1[2]));
                // D2 += P V
                #pragma unroll
                for (int j = 0; j < 8; j++)
                    MMA_BF16(d2[i][j], pa0, pa1, pa2, pa3, vb[j][0], vb[j][1]);
            }
        }
    }

    // reduce l across the 4 threads sharing each row
    #pragma unroll
    for (int r = 0; r < 4; r++) {
        lrow[r] += __shfl_xor_sync(0xffffffffu, lrow[r], 1);
        lrow[r] += __shfl_xor_sync(0xffffffffu, lrow[r], 2);
    }
    float gm = gamma[0];
    float inv[4];
    #pragma unroll
    for (int r = 0; r < 4; r++) inv[r] = gm / lrow[r];

    // epilogue: out[b][c][q] = scale * D2 + cnn
    const float* cb = cnn + (size_t)b * CC * NN;
    float* ob = out + (size_t)b * CC * NN;
    #pragma unroll
    for (int i = 0; i < 2; i++) {
        int q0 = qbase + i * 16 + g;
        #pragma unroll
        for (int j = 0; j < 8; j++) {
            int ch = j * 8 + 2 * tp;
            ob[(size_t)ch * NN + q0]            = d2[i][j][0] * inv[2 * i]     + cb[(size_t)ch * NN + q0];
            ob[(size_t)(ch + 1) * NN + q0]      = d2[i][j][1] * inv[2 * i]     + cb[(size_t)(ch + 1) * NN + q0];
            ob[(size_t)ch * NN + q0 + 8]        = d2[i][j][2] * inv[2 * i + 1] + cb[(size_t)ch * NN + q0 + 8];
            ob[(size_t)(ch + 1) * NN + q0 + 8]  = d2[i][j][3] * inv[2 * i + 1] + cb[(size_t)(ch + 1) * NN + q0 + 8];
        }
    }
}

// ---------------- launch -------------------------------------------------------
extern "C" void kernel_launch(void* const* d_in, const int* in_sizes, int n_in,
                              void* d_out, int out_size) {
    const float* cnn   = (const float*)d_in[0];
    const float* vit   = (const float*)d_in[1];
    const float* Wq    = (const float*)d_in[2];
    const float* bq    = (const float*)d_in[3];
    const float* Wk    = (const float*)d_in[4];
    const float* bk    = (const float*)d_in[5];
    const float* Wv    = (const float*)d_in[6];
    const float* bv    = (const float*)d_in[7];
    const float* gamma = (const float*)d_in[8];
    const float* gcnn  = (const float*)d_in[9];
    const float* gvit  = (const float*)d_in[10];
    float* out = (float*)d_out;

    k_gram    <<<dim3(NCHUNK, NIMG), 256>>>(cnn, vit);
    k_softmaxA<<<NIMG, 256>>>();
    k_applyA  <<<dim3(NCHUNK, NIMG), 256>>>(cnn, vit, gcnn, gvit);
    k_qk      <<<dim3(NN / 128, BB, 2), 256>>>(Wq, bq, Wk, bk);
    k_vproj   <<<dim3(NN / 64, BB), 256>>>(Wv, bv);
    k_attn    <<<dim3(NN / 128, BB), 128>>>(gamma, cnn, out);
}

// round 4
// speedup vs baseline: 3.1380x; 1.1430x over previous
#include <cuda_runtime.h>
#include <cuda_bf16.h>
#include <cuda_fp16.h>
#include <cstdint>

// Problem constants
#define BB 4
#define CC 64
#define NN 4096
#define C8V 8
#define NIMG 8
#define NCHUNK 32

// ---------------- scratch ----------------------------------------------------
__device__ float g_gpart[NCHUNK * NIMG * CC * CC];
__device__ float g_At[NIMG * CC * CC];             // A transposed: [img][d][r]
__device__ float g_ycnn[BB * CC * NN];
__device__ float g_yvit[BB * CC * NN];
__device__ float g_WqkT[2 * CC * C8V];             // [z][c][o]
__device__ float g_WvT[CC * CC];                   // [c][o]
__device__ __nv_bfloat16 g_qb[BB * NN * C8V];      // [b][n][8] (prescaled 1/ln2)
__device__ __nv_bfloat16 g_kb[BB * NN * C8V];      // [b][n][8]
__device__ __half        g_v [BB * NN * CC];       // [b][n][c]

__device__ __forceinline__ uint32_t smem_u32(const void* p) {
    uint32_t a;
    asm("{ .reg .u64 t; cvta.to.shared.u64 t, %1; cvt.u32.u64 %0, t; }" : "=r"(a) : "l"(p));
    return a;
}

#define MMA_BF16_K8(d, a0, a1, b0)                                                 \
    asm volatile("mma.sync.aligned.m16n8k8.row.col.f32.bf16.bf16.f32 "             \
        "{%0,%1,%2,%3}, {%4,%5}, {%6}, {%0,%1,%2,%3};"                             \
        : "+f"((d)[0]), "+f"((d)[1]), "+f"((d)[2]), "+f"((d)[3])                   \
        : "r"(a0), "r"(a1), "r"(b0))

#define MMA_F16(d, a0, a1, a2, a3, b0, b1)                                         \
    asm volatile("mma.sync.aligned.m16n8k16.row.col.f32.f16.f16.f32 "              \
        "{%0,%1,%2,%3}, {%4,%5,%6,%7}, {%8,%9}, {%0,%1,%2,%3};"                    \
        : "+f"((d)[0]), "+f"((d)[1]), "+f"((d)[2]), "+f"((d)[3])                   \
        : "r"(a0), "r"(a1), "r"(a2), "r"(a3), "r"(b0), "r"(b1))

#define CP16(dst, src) asm volatile("cp.async.cg.shared.global [%0], [%1], 16;" :: "r"(dst), "l"(src) : "memory")
#define CP_COMMIT()    asm volatile("cp.async.commit_group;" ::: "memory")

// ---------------- Stage 0: transpose weights ----------------------------------
__global__ void k_transW(const float* __restrict__ Wq, const float* __restrict__ Wk,
                         const float* __restrict__ Wv) {
    int t = threadIdx.x;
    for (int i = t; i < C8V * CC; i += 256) {
        int o = i >> 6, c = i & 63;
        g_WqkT[c * C8V + o] = Wq[i];
        g_WqkT[CC * C8V + c * C8V + o] = Wk[i];
    }
    for (int i = t; i < CC * CC; i += 256) {
        int o = i >> 6, c = i & 63;
        g_WvT[c * CC + o] = Wv[i];
    }
}

// ---------------- Stage A1: gram partials (4x4 register tiles) -----------------
__global__ void k_gram(const float* __restrict__ cnn, const float* __restrict__ vit) {
    int chunk = blockIdx.x, img = blockIdx.y;
    const float* x = (img < BB) ? (cnn + img * CC * NN) : (vit + (img - BB) * CC * NN);
    __shared__ float xs[CC][132];
    int n0 = chunk * 128;
    for (int i = threadIdx.x; i < CC * 128; i += 256) {
        int c = i >> 7, j = i & 127;
        xs[c][j] = x[c * NN + n0 + j];
    }
    __syncthreads();
    int tx = threadIdx.x & 15, ty = threadIdx.x >> 4;
    int ci0 = ty * 4, cj0 = tx * 4;
    float acc[4][4];
    #pragma unroll
    for (int i = 0; i < 4; i++)
        #pragma unroll
        for (int j = 0; j < 4; j++) acc[i][j] = 0.f;
    for (int j = 0; j < 128; j += 4) {
        float4 a[4], bvv[4];
        #pragma unroll
        for (int i = 0; i < 4; i++) a[i] = *(const float4*)&xs[ci0 + i][j];
        #pragma unroll
        for (int i = 0; i < 4; i++) bvv[i] = *(const float4*)&xs[cj0 + i][j];
        #pragma unroll
        for (int i = 0; i < 4; i++)
            #pragma unroll
            for (int jj = 0; jj < 4; jj++)
                acc[i][jj] += a[i].x * bvv[jj].x + a[i].y * bvv[jj].y
                            + a[i].z * bvv[jj].z + a[i].w * bvv[jj].w;
    }
    float* outp = g_gpart + (chunk * NIMG + img) * CC * CC;
    #pragma unroll
    for (int i = 0; i < 4; i++)
        *(float4*)&outp[(ci0 + i) * CC + cj0] =
            make_float4(acc[i][0], acc[i][1], acc[i][2], acc[i][3]);
}

// ---------------- Stage A2: A^T = softmax(-G)^T --------------------------------
__global__ void k_softmaxA() {
    int img = blockIdx.x;
    __shared__ float Gs[CC * CC];
    for (int p = threadIdx.x; p < CC * CC; p += 256) {
        float s = 0.f;
        #pragma unroll
        for (int ch = 0; ch < NCHUNK; ch++)
            s += g_gpart[(ch * NIMG + img) * CC * CC + p];
        Gs[p] = s;
    }
    __syncthreads();
    if (threadIdx.x < CC) {
        int r = threadIdx.x;
        float m = -1e30f;
        for (int d = 0; d < CC; d++) m = fmaxf(m, -Gs[r * CC + d]);
        float sum = 0.f;
        for (int d = 0; d < CC; d++) sum += __expf(-Gs[r * CC + d] - m);
        float inv = 1.f / sum;
        for (int d = 0; d < CC; d++)
            g_At[img * CC * CC + d * CC + r] = __expf(-Gs[r * CC + d] - m) * inv;  // transposed
    }
}

// ---------------- Stage A3: y = gamma_cla*(A@x)+x (8ch x 4n tiles) -------------
__global__ void k_applyA(const float* __restrict__ cnn, const float* __restrict__ vit,
                         const float* __restrict__ gcnn, const float* __restrict__ gvit) {
    int chunk = blockIdx.x, img = blockIdx.y;
    const float* x; float* y; float g;
    if (img < BB) { x = cnn + img * CC * NN; y = g_ycnn + img * CC * NN; g = gcnn[0]; }
    else          { x = vit + (img - BB) * CC * NN; y = g_yvit + (img - BB) * CC * NN; g = gvit[0]; }
    __shared__ float xs[CC][128];
    int n0 = chunk * 128;
    for (int i = threadIdx.x; i < CC * 128; i += 256) {
        int c = i >> 7, j = i & 127;
        xs[c][j] = x[c * NN + n0 + j];
    }
    __syncthreads();
    int nq = threadIdx.x & 31, cg = threadIdx.x >> 5;
    int ch0 = cg * 8;
    const float* At = g_At + img * CC * CC;
    float4 acc[8];
    #pragma unroll
    for (int i = 0; i < 8; i++) acc[i] = make_float4(0.f, 0.f, 0.f, 0.f);
    #pragma unroll 4
    for (int d = 0; d < CC; d++) {
        float4 xv = *(const float4*)&xs[d][nq * 4];
        float4 A0 = *(const float4*)&At[d * CC + ch0];       // uniform across warp
        float4 A1 = *(const float4*)&At[d * CC + ch0 + 4];
        float av[8] = {A0.x, A0.y, A0.z, A0.w, A1.x, A1.y, A1.z, A1.w};
        #pragma unroll
        for (int i = 0; i < 8; i++) {
            acc[i].x += av[i] * xv.x; acc[i].y += av[i] * xv.y;
            acc[i].z += av[i] * xv.z; acc[i].w += av[i] * xv.w;
        }
    }
    #pragma unroll
    for (int i = 0; i < 8; i++) {
        float4 r = *(const float4*)&xs[ch0 + i][nq * 4];
        float4 o = make_float4(g * acc[i].x + r.x, g * acc[i].y + r.y,
                               g * acc[i].z + r.z, g * acc[i].w + r.w);
        *(float4*)&y[(ch0 + i) * NN + n0 + nq * 4] = o;
    }
}

// ---------------- Stage B1: q / k projections (register-only) ------------------
__global__ void k_qk(const float* __restrict__ bq, const float* __restrict__ bk) {
    int n0 = blockIdx.x * 128, b = blockIdx.y, z = blockIdx.z;
    const float* src = (z == 0) ? (g_ycnn + b * CC * NN) : (g_yvit + b * CC * NN);
    const float* Wt = g_WqkT + z * CC * C8V;
    const float* bias = (z == 0) ? bq : bk;
    __nv_bfloat16* dst = (z == 0) ? g_qb : g_kb;
    float postscale = (z == 0) ? 1.4426950408889634f : 1.0f;
    int n = n0 + threadIdx.x;
    float acc[8];
    #pragma unroll
    for (int o = 0; o < 8; o++) acc[o] = bias[o];
    #pragma unroll 4
    for (int c = 0; c < CC; c++) {
        float xv = src[c * NN + n];
        float4 w0 = *(const float4*)&Wt[c * C8V];
        float4 w1 = *(const float4*)&Wt[c * C8V + 4];
        acc[0] += w0.x * xv; acc[1] += w0.y * xv; acc[2] += w0.z * xv; acc[3] += w0.w * xv;
        acc[4] += w1.x * xv; acc[5] += w1.y * xv; acc[6] += w1.z * xv; acc[7] += w1.w * xv;
    }
    ushort4 u0, u1;
    u0.x = __bfloat16_as_ushort(__float2bfloat16(acc[0] * postscale));
    u0.y = __bfloat16_as_ushort(__float2bfloat16(acc[1] * postscale));
    u0.z = __bfloat16_as_ushort(__float2bfloat16(acc[2] * postscale));
    u0.w = __bfloat16_as_ushort(__float2bfloat16(acc[3] * postscale));
    u1.x = __bfloat16_as_ushort(__float2bfloat16(acc[4] * postscale));
    u1.y = __bfloat16_as_ushort(__float2bfloat16(acc[5] * postscale));
    u1.z = __bfloat16_as_ushort(__float2bfloat16(acc[6] * postscale));
    u1.w = __bfloat16_as_ushort(__float2bfloat16(acc[7] * postscale));
    *(ushort4*)(dst + ((size_t)(b * NN + n)) * 8)     = u0;
    *(ushort4*)(dst + ((size_t)(b * NN + n)) * 8 + 4) = u1;
}

// ---------------- Stage B2: v projection -> half [b][n][c] ---------------------
__global__ void k_vproj(const float* __restrict__ bv) {
    int n0 = blockIdx.x * 64, b = blockIdx.y;
    int n = n0 + (threadIdx.x & 63);
    int og = (threadIdx.x >> 6) * 16;
    const float* yv = g_yvit + b * CC * NN;
    float acc[16];
    #pragma unroll
    for (int i = 0; i < 16; i++) acc[i] = bv[og + i];
    #pragma unroll 4
    for (int c = 0; c < CC; c++) {
        float xv = yv[c * NN + n];
        #pragma unroll
        for (int m = 0; m < 4; m++) {
            float4 w = *(const float4*)&g_WvT[c * CC + og + m * 4];
            acc[m * 4 + 0] += w.x * xv; acc[m * 4 + 1] += w.y * xv;
            acc[m * 4 + 2] += w.z * xv; acc[m * 4 + 3] += w.w * xv;
        }
    }
    __half* dst = g_v + ((size_t)(b * NN + n)) * CC + og;
    #pragma unroll
    for (int m = 0; m < 2; m++) {
        ushort4 u;
        u.x = __half_as_ushort(__float2half(acc[m * 8 + 0]));
        u.y = __half_as_ushort(__float2half(acc[m * 8 + 1]));
        u.z = __half_as_ushort(__float2half(acc[m * 8 + 2]));
        u.w = __half_as_ushort(__float2half(acc[m * 8 + 3]));
        ushort4 v;
        v.x = __half_as_ushort(__float2half(acc[m * 8 + 4]));
        v.y = __half_as_ushort(__float2half(acc[m * 8 + 5]));
        v.z = __half_as_ushort(__float2half(acc[m * 8 + 6]));
        v.w = __half_as_ushort(__float2half(acc[m * 8 + 7]));
        *(ushort4*)(dst + m * 8)     = u;
        *(ushort4*)(dst + m * 8 + 4) = v;
    }
}

// ---------------- Stage C: mma attention, cp.async pipelined -------------------
__global__ void __launch_bounds__(128) k_attn(const float* __restrict__ gamma,
                                              const float* __restrict__ cnn,
                                              float* __restrict__ out) {
    int qt = blockIdx.x, b = blockIdx.y;
    int tid = threadIdx.x;
    int w = tid >> 5, lane = tid & 31;
    int g = lane >> 2, tp = lane & 3;

    __shared__ __align__(16) __nv_bfloat16 Ks[2][128][8];
    __shared__ __align__(16) __half        Vs[2][128][72];

    int qbase = qt * 128 + w * 32;
    uint32_t qa[2][2];
    #pragma unroll
    for (int i = 0; i < 2; i++) {
        qa[i][0] = *(const uint32_t*)(g_qb + ((size_t)(b * NN + qbase + i * 16 + g)) * 8 + 2 * tp);
        qa[i][1] = *(const uint32_t*)(g_qb + ((size_t)(b * NN + qbase + i * 16 + g + 8)) * 8 + 2 * tp);
    }

    float d2[2][8][4];
    #pragma unroll
    for (int i = 0; i < 2; i++)
        #pragma unroll
        for (int j = 0; j < 8; j++)
            #pragma unroll
            for (int r = 0; r < 4; r++) d2[i][j][r] = 0.f;
    float lrow[4] = {0.f, 0.f, 0.f, 0.f};

    // prologue: load tile 0
    {
        int k0 = 0;
        CP16(smem_u32(&Ks[0][tid][0]), g_kb + ((size_t)(b * NN + k0 + tid)) * 8);
        #pragma unroll
        for (int i2 = 0; i2 < 8; i2++) {
            int idx = tid + i2 * 128, key = idx >> 3, c8 = (idx & 7) * 8;
            CP16(smem_u32(&Vs[0][key][c8]), g_v + ((size_t)(b * NN + k0 + key)) * CC + c8);
        }
        CP_COMMIT();
    }

    for (int t = 0; t < 32; t++) {
        if (t + 1 < 32) {
            int nb = (t + 1) & 1, k0 = (t + 1) * 128;
            CP16(smem_u32(&Ks[nb][tid][0]), g_kb + ((size_t)(b * NN + k0 + tid)) * 8);
            #pragma unroll
            for (int i2 = 0; i2 < 8; i2++) {
                int idx = tid + i2 * 128, key = idx >> 3, c8 = (idx & 7) * 8;
                CP16(smem_u32(&Vs[nb][key][c8]), g_v + ((size_t)(b * NN + k0 + key)) * CC + c8);
            }
            CP_COMMIT();
            asm volatile("cp.async.wait_group 1;" ::: "memory");
        } else {
            asm volatile("cp.async.wait_group 0;" ::: "memory");
        }
        __syncthreads();
        int bs = t & 1;

        for (int kc = 0; kc < 8; kc++) {
            uint32_t kb0, kb1;
            {
                uint32_t addr = smem_u32(&Ks[bs][kc * 16 + (lane & 15)][0]);
                asm volatile("ldmatrix.sync.aligned.m8n8.x2.shared.b16 {%0,%1}, [%2];"
                             : "=r"(kb0), "=r"(kb1) : "r"(addr));
            }
            uint32_t vb[8][2];
            #pragma unroll
            for (int m = 0; m < 4; m++) {
                uint32_t addr = smem_u32(&Vs[bs][kc * 16 + (lane & 15)][(lane >> 4) * 8 + m * 16]);
                asm volatile("ldmatrix.sync.aligned.m8n8.x4.trans.shared.b16 {%0,%1,%2,%3}, [%4];"
                             : "=r"(vb[2 * m][0]), "=r"(vb[2 * m][1]),
                               "=r"(vb[2 * m + 1][0]), "=r"(vb[2 * m + 1][1])
                             : "r"(addr));
            }
            #pragma unroll
            for (int i = 0; i < 2; i++) {
                float s0[4] = {0.f, 0.f, 0.f, 0.f}, s1[4] = {0.f, 0.f, 0.f, 0.f};
                MMA_BF16_K8(s0, qa[i][0], qa[i][1], kb0);
                MMA_BF16_K8(s1, qa[i][0], qa[i][1], kb1);
                // P = 2^S in packed fp16
                uint32_t pa0, pa1, pa2, pa3;
                asm("cvt.rn.f16x2.f32 %0, %1, %2;" : "=r"(pa0) : "f"(s0[1]), "f"(s0[0]));
                asm("cvt.rn.f16x2.f32 %0, %1, %2;" : "=r"(pa1) : "f"(s0[3]), "f"(s0[2]));
                asm("cvt.rn.f16x2.f32 %0, %1, %2;" : "=r"(pa2) : "f"(s1[1]), "f"(s1[0]));
                asm("cvt.rn.f16x2.f32 %0, %1, %2;" : "=r"(pa3) : "f"(s1[3]), "f"(s1[2]));
                asm("ex2.approx.f16x2 %0, %0;" : "+r"(pa0));
                asm("ex2.approx.f16x2 %0, %0;" : "+r"(pa1));
                asm("ex2.approx.f16x2 %0, %0;" : "+r"(pa2));
                asm("ex2.approx.f16x2 %0, %0;" : "+r"(pa3));
                // l accumulation
                uint32_t h0, h1;
                asm("add.rn.f16x2 %0, %1, %2;" : "=r"(h0) : "r"(pa0), "r"(pa2));
                asm("add.rn.f16x2 %0, %1, %2;" : "=r"(h1) : "r"(pa1), "r"(pa3));
                float2 f0 = __half22float2(*reinterpret_cast<__half2*>(&h0));
                float2 f1 = __half22float2(*reinterpret_cast<__half2*>(&h1));
                lrow[2 * i]     += f0.x + f0.y;
                lrow[2 * i + 1] += f1.x + f1.y;
                #pragma unroll
                for (int j = 0; j < 8; j++)
                    MMA_F16(d2[i][j], pa0, pa1, pa2, pa3, vb[j][0], vb[j][1]);
            }
        }
        __syncthreads();
    }

    #pragma unroll
    for (int r = 0; r < 4; r++) {
        lrow[r] += __shfl_xor_sync(0xffffffffu, lrow[r], 1);
        lrow[r] += __shfl_xor_sync(0xffffffffu, lrow[r], 2);
    }
    float gm = gamma[0];
    float inv[4];
    #pragma unroll
    for (int r = 0; r < 4; r++) inv[r] = gm / lrow[r];

    const float* cb = cnn + (size_t)b * CC * NN;
    float* ob = out + (size_t)b * CC * NN;
    #pragma unroll
    for (int i = 0; i < 2; i++) {
        int q0 = qbase + i * 16 + g;
        #pragma unroll
        for (int j = 0; j < 8; j++) {
            int ch = j * 8 + 2 * tp;
            ob[(size_t)ch * NN + q0]           = d2[i][j][0] * inv[2 * i]     + cb[(size_t)ch * NN + q0];
            ob[(size_t)(ch + 1) * NN + q0]     = d2[i][j][1] * inv[2 * i]     + cb[(size_t)(ch + 1) * NN + q0];
            ob[(size_t)ch * NN + q0 + 8]       = d2[i][j][2] * inv[2 * i + 1] + cb[(size_t)ch * NN + q0 + 8];
            ob[(size_t)(ch + 1) * NN + q0 + 8] = d2[i][j][3] * inv[2 * i + 1] + cb[(size_t)(ch + 1) * NN + q0 + 8];
        }
    }
}

// ---------------- launch ---------------------------------------------------------
extern "C" void kernel_launch(void* const* d_in, const int* in_sizes, int n_in,
                              void* d_out, int out_size) {
    const float* cnn   = (const float*)d_in[0];
    const float* vit   = (const float*)d_in[1];
    const float* Wq    = (const float*)d_in[2];
    const float* bq    = (const float*)d_in[3];
    const float* Wk    = (const float*)d_in[4];
    const float* bk    = (const float*)d_in[5];
    const float* Wv    = (const float*)d_in[6];
    const float* bv    = (const float*)d_in[7];
    const float* gamma = (const float*)d_in[8];
    const float* gcnn  = (const float*)d_in[9];
    const float* gvit  = (const float*)d_in[10];
    float* out = (float*)d_out;

    k_transW  <<<1, 256>>>(Wq, Wk, Wv);
    k_gram    <<<dim3(NCHUNK, NIMG), 256>>>(cnn, vit);
    k_softmaxA<<<NIMG, 256>>>();
    k_applyA  <<<dim3(NCHUNK, NIMG), 256>>>(cnn, vit, gcnn, gvit);
    k_qk      <<<dim3(NN / 128, BB, 2), 128>>>(bq, bk);
    k_vproj   <<<dim3(NN / 64, BB), 256>>>(bv);
    k_attn    <<<dim3(NN / 128, BB), 128>>>(gamma, cnn, out);
}

// round 5
// speedup vs baseline: 3.6531x; 1.1642x over previous
#include <cuda_runtime.h>
#include <cuda_bf16.h>
#include <cuda_fp16.h>
#include <cstdint>

// Problem constants
#define BB 4
#define CC 64
#define NN 4096
#define C8V 8
#define NIMG 8
#define NCHUNK 32
#define RLN2 1.4426950408889634f

// ---------------- scratch ----------------------------------------------------
__device__ float g_gpart[NCHUNK * NIMG * CC * CC];
__device__ float g_WqT[BB * CC * C8V];             // [b][c][o], prescaled by 1/ln2
__device__ float g_WkT[BB * CC * C8V];             // [b][c][o]
__device__ float g_WvTe[BB * CC * CC];             // [b][c][o]
__device__ __nv_bfloat16 g_qb[BB * NN * C8V];      // [b][n][8] (prescaled 1/ln2)
__device__ __nv_bfloat16 g_kb[BB * NN * C8V];      // [b][n][8]
__device__ __half        g_v [BB * NN * CC];       // [b][n][c]

__device__ __forceinline__ uint32_t smem_u32(const void* p) {
    uint32_t a;
    asm("{ .reg .u64 t; cvta.to.shared.u64 t, %1; cvt.u32.u64 %0, t; }" : "=r"(a) : "l"(p));
    return a;
}

#define MMA_BF16_K8(d, a0, a1, b0)                                                 \
    asm volatile("mma.sync.aligned.m16n8k8.row.col.f32.bf16.bf16.f32 "             \
        "{%0,%1,%2,%3}, {%4,%5}, {%6}, {%0,%1,%2,%3};"                             \
        : "+f"((d)[0]), "+f"((d)[1]), "+f"((d)[2]), "+f"((d)[3])                   \
        : "r"(a0), "r"(a1), "r"(b0))

#define MMA_F16(d, a0, a1, a2, a3, b0, b1)                                         \
    asm volatile("mma.sync.aligned.m16n8k16.row.col.f32.f16.f16.f32 "              \
        "{%0,%1,%2,%3}, {%4,%5,%6,%7}, {%8,%9}, {%0,%1,%2,%3};"                    \
        : "+f"((d)[0]), "+f"((d)[1]), "+f"((d)[2]), "+f"((d)[3])                   \
        : "r"(a0), "r"(a1), "r"(a2), "r"(a3), "r"(b0), "r"(b1))

#define CP16(dst, src) asm volatile("cp.async.cg.shared.global [%0], [%1], 16;" :: "r"(dst), "l"(src) : "memory")
#define CP_COMMIT()    asm volatile("cp.async.commit_group;" ::: "memory")

// ---------------- Stage A1: gram partials (4x4 register tiles) -----------------
__global__ void k_gram(const float* __restrict__ cnn, const float* __restrict__ vit) {
    int chunk = blockIdx.x, img = blockIdx.y;
    const float* x = (img < BB) ? (cnn + img * CC * NN) : (vit + (img - BB) * CC * NN);
    __shared__ float xs[CC][132];
    int n0 = chunk * 128;
    for (int i = threadIdx.x; i < CC * 128; i += 256) {
        int c = i >> 7, j = i & 127;
        xs[c][j] = x[c * NN + n0 + j];
    }
    __syncthreads();
    int tx = threadIdx.x & 15, ty = threadIdx.x >> 4;
    int ci0 = ty * 4, cj0 = tx * 4;
    float acc[4][4];
    #pragma unroll
    for (int i = 0; i < 4; i++)
        #pragma unroll
        for (int j = 0; j < 4; j++) acc[i][j] = 0.f;
    for (int j = 0; j < 128; j += 4) {
        float4 a[4], bvv[4];
        #pragma unroll
        for (int i = 0; i < 4; i++) a[i] = *(const float4*)&xs[ci0 + i][j];
        #pragma unroll
        for (int i = 0; i < 4; i++) bvv[i] = *(const float4*)&xs[cj0 + i][j];
        #pragma unroll
        for (int i = 0; i < 4; i++)
            #pragma unroll
            for (int jj = 0; jj < 4; jj++)
                acc[i][jj] += a[i].x * bvv[jj].x + a[i].y * bvv[jj].y
                            + a[i].z * bvv[jj].z + a[i].w * bvv[jj].w;
    }
    float* outp = g_gpart + (chunk * NIMG + img) * CC * CC;
    #pragma unroll
    for (int i = 0; i < 4; i++)
        *(float4*)&outp[(ci0 + i) * CC + cj0] =
            make_float4(acc[i][0], acc[i][1], acc[i][2], acc[i][3]);
}

// ---------------- Stage A2: reduce + softmax + effective-weight compose --------
// grid 8 (img), 256 threads. img<4: Wq_eff for batch img (cnn A).
// img>=4: Wk_eff, Wv_eff for batch img-4 (vit A).
__global__ void k_prep(const float* __restrict__ Wq, const float* __restrict__ Wk,
                       const float* __restrict__ Wv,
                       const float* __restrict__ gcnn, const float* __restrict__ gvit) {
    int img = blockIdx.x;
    int tid = threadIdx.x;
    __shared__ __align__(16) float As[CC * CC];        // G, then A in place
    __shared__ __align__(16) float Wvs[CC * 68];       // W transposed [c][o], padded
    __shared__ float Wqs[CC * C8V];                    // small W transposed [c][o]

    // reduce gram partials -> G
    for (int p = tid; p < CC * CC; p += 256) {
        float s = 0.f;
        #pragma unroll
        for (int ch = 0; ch < NCHUNK; ch++)
            s += g_gpart[(ch * NIMG + img) * CC * CC + p];
        As[p] = s;
    }
    __syncthreads();

    // softmax(-G) row-wise, 4 threads per row
    {
        int r = tid >> 2, l4 = tid & 3;
        float m = -1e30f;
        for (int d = l4; d < CC; d += 4) m = fmaxf(m, -As[r * CC + d]);
        m = fmaxf(m, __shfl_xor_sync(0xffffffffu, m, 1));
        m = fmaxf(m, __shfl_xor_sync(0xffffffffu, m, 2));
        float s = 0.f;
        for (int d = l4; d < CC; d += 4) s += __expf(-As[r * CC + d] - m);
        s += __shfl_xor_sync(0xffffffffu, s, 1);
        s += __shfl_xor_sync(0xffffffffu, s, 2);
        float inv = 1.f / s;
        for (int d = l4; d < CC; d += 4)
            As[r * CC + d] = __expf(-As[r * CC + d] - m) * inv;
    }

    // load small W (q or k) transposed: Wqs[c][o]
    const float* Wsm = (img < BB) ? Wq : Wk;
    for (int i = tid; i < C8V * CC; i += 256)
        Wqs[(i & 63) * C8V + (i >> 6)] = Wsm[i];
    if (img >= BB) {
        for (int i = tid; i < CC * CC; i += 256)
            Wvs[(i & 63) * 68 + (i >> 6)] = Wv[i];
    }
    __syncthreads();

    if (img < BB) {
        // Wq_eff[o][d] = Wq[o][d] + g*sum_c Wq[o][c] A[c][d]; store T, scaled 1/ln2
        float g = gcnn[0];
        for (int p = tid; p < CC * C8V; p += 256) {
            int d = p >> 3, o = p & 7;
            float s = 0.f;
            #pragma unroll 4
            for (int c = 0; c < CC; c++) s += Wqs[c * C8V + o] * As[c * CC + d];
            g_WqT[img * CC * C8V + d * C8V + o] = (Wqs[d * C8V + o] + g * s) * RLN2;
        }
    } else {
        int b = img - BB;
        float g = gvit[0];
        // Wk_eff
        for (int p = tid; p < CC * C8V; p += 256) {
            int d = p >> 3, o = p & 7;
            float s = 0.f;
            #pragma unroll 4
            for (int c = 0; c < CC; c++) s += Wqs[c * C8V + o] * As[c * CC + d];
            g_WkT[b * CC * C8V + d * C8V + o] = Wqs[d * C8V + o] + g * s;
        }
        // Wv_eff, 4x4 register tiles
        int tx = tid & 15, ty = tid >> 4;
        int o0 = tx * 4, d0 = ty * 4;
        float acc[4][4];
        #pragma unroll
        for (int i = 0; i < 4; i++)
            #pragma unroll
            for (int j = 0; j < 4; j++) acc[i][j] = 0.f;
        for (int c = 0; c < CC; c++) {
            float4 a = *(const float4*)&As[c * CC + d0];
            float4 wv = *(const float4*)&Wvs[c * 68 + o0];
            float ar[4] = {a.x, a.y, a.z, a.w};
            float wr[4] = {wv.x, wv.y, wv.z, wv.w};
            #pragma unroll
            for (int i = 0; i < 4; i++)
                #pragma unroll
                for (int j = 0; j < 4; j++) acc[i][j] += ar[i] * wr[j];
        }
        #pragma unroll
        for (int i = 0; i < 4; i++) {
            float4 wd = *(const float4*)&Wvs[(d0 + i) * 68 + o0];
            float4 o = make_float4(wd.x + g * acc[i][0], wd.y + g * acc[i][1],
                                   wd.z + g * acc[i][2], wd.w + g * acc[i][3]);
            *(float4*)&g_WvTe[b * CC * CC + (d0 + i) * CC + o0] = o;
        }
    }
}

// ---------------- Stage B1: q / k projections (raw inputs, eff weights) --------
__global__ void k_qk(const float* __restrict__ cnn, const float* __restrict__ vit,
                     const float* __restrict__ bq, const float* __restrict__ bk) {
    int n0 = blockIdx.x * 128, b = blockIdx.y, z = blockIdx.z;
    const float* src = ((z == 0) ? cnn : vit) + (size_t)b * CC * NN;
    const float* Wt = ((z == 0) ? g_WqT : g_WkT) + b * CC * C8V;
    const float* bias = (z == 0) ? bq : bk;
    __nv_bfloat16* dst = (z == 0) ? g_qb : g_kb;
    float bscale = (z == 0) ? RLN2 : 1.0f;
    int n = n0 + threadIdx.x;
    float acc[8];
    #pragma unroll
    for (int o = 0; o < 8; o++) acc[o] = bias[o] * bscale;
    #pragma unroll 8
    for (int c = 0; c < CC; c++) {
        float xv = src[c * NN + n];
        float4 w0 = *(const float4*)&Wt[c * C8V];
        float4 w1 = *(const float4*)&Wt[c * C8V + 4];
        acc[0] += w0.x * xv; acc[1] += w0.y * xv; acc[2] += w0.z * xv; acc[3] += w0.w * xv;
        acc[4] += w1.x * xv; acc[5] += w1.y * xv; acc[6] += w1.z * xv; acc[7] += w1.w * xv;
    }
    ushort4 u0, u1;
    u0.x = __bfloat16_as_ushort(__float2bfloat16(acc[0]));
    u0.y = __bfloat16_as_ushort(__float2bfloat16(acc[1]));
    u0.z = __bfloat16_as_ushort(__float2bfloat16(acc[2]));
    u0.w = __bfloat16_as_ushort(__float2bfloat16(acc[3]));
    u1.x = __bfloat16_as_ushort(__float2bfloat16(acc[4]));
    u1.y = __bfloat16_as_ushort(__float2bfloat16(acc[5]));
    u1.z = __bfloat16_as_ushort(__float2bfloat16(acc[6]));
    u1.w = __bfloat16_as_ushort(__float2bfloat16(acc[7]));
    *(ushort4*)(dst + ((size_t)(b * NN + n)) * 8)     = u0;
    *(ushort4*)(dst + ((size_t)(b * NN + n)) * 8 + 4) = u1;
}

// ---------------- Stage B2: v projection -> half [b][n][c] ---------------------
__global__ void k_vproj(const float* __restrict__ vit, const float* __restrict__ bv) {
    int n0 = blockIdx.x * 64, b = blockIdx.y;
    int n = n0 + (threadIdx.x & 63);
    int og = (threadIdx.x >> 6) * 16;
    const float* yv = vit + (size_t)b * CC * NN;
    const float* Wt = g_WvTe + b * CC * CC;
    float acc[16];
    #pragma unroll
    for (int i = 0; i < 16; i++) acc[i] = bv[og + i];
    #pragma unroll 4
    for (int c = 0; c < CC; c++) {
        float xv = yv[c * NN + n];
        #pragma unroll
        for (int m = 0; m < 4; m++) {
            float4 w = *(const float4*)&Wt[c * CC + og + m * 4];
            acc[m * 4 + 0] += w.x * xv; acc[m * 4 + 1] += w.y * xv;
            acc[m * 4 + 2] += w.z * xv; acc[m * 4 + 3] += w.w * xv;
        }
    }
    __half* dst = g_v + ((size_t)(b * NN + n)) * CC + og;
    #pragma unroll
    for (int m = 0; m < 2; m++) {
        ushort4 u;
        u.x = __half_as_ushort(__float2half(acc[m * 8 + 0]));
        u.y = __half_as_ushort(__float2half(acc[m * 8 + 1]));
        u.z = __half_as_ushort(__float2half(acc[m * 8 + 2]));
        u.w = __half_as_ushort(__float2half(acc[m * 8 + 3]));
        ushort4 v;
        v.x = __half_as_ushort(__float2half(acc[m * 8 + 4]));
        v.y = __half_as_ushort(__float2half(acc[m * 8 + 5]));
        v.z = __half_as_ushort(__float2half(acc[m * 8 + 6]));
        v.w = __half_as_ushort(__float2half(acc[m * 8 + 7]));
        *(ushort4*)(dst + m * 8)     = u;
        *(ushort4*)(dst + m * 8 + 4) = v;
    }
}

// ---------------- Stage C: mma attention, cp.async pipelined -------------------
__global__ void __launch_bounds__(128) k_attn(const float* __restrict__ gamma,
                                              const float* __restrict__ cnn,
                                              float* __restrict__ out) {
    int qt = blockIdx.x, b = blockIdx.y;
    int tid = threadIdx.x;
    int w = tid >> 5, lane = tid & 31;
    int g = lane >> 2, tp = lane & 3;

    __shared__ __align__(16) __nv_bfloat16 Ks[2][128][8];
    __shared__ __align__(16) __half        Vs[2][128][72];

    int qbase = qt * 128 + w * 32;
    uint32_t qa[2][2];
    #pragma unroll
    for (int i = 0; i < 2; i++) {
        qa[i][0] = *(const uint32_t*)(g_qb + ((size_t)(b * NN + qbase + i * 16 + g)) * 8 + 2 * tp);
        qa[i][1] = *(const uint32_t*)(g_qb + ((size_t)(b * NN + qbase + i * 16 + g + 8)) * 8 + 2 * tp);
    }

    float d2[2][8][4];
    #pragma unroll
    for (int i = 0; i < 2; i++)
        #pragma unroll
        for (int j = 0; j < 8; j++)
            #pragma unroll
            for (int r = 0; r < 4; r++) d2[i][j][r] = 0.f;
    float lrow[4] = {0.f, 0.f, 0.f, 0.f};

    {
        int k0 = 0;
        CP16(smem_u32(&Ks[0][tid][0]), g_kb + ((size_t)(b * NN + k0 + tid)) * 8);
        #pragma unroll
        for (int i2 = 0; i2 < 8; i2++) {
            int idx = tid + i2 * 128, key = idx >> 3, c8 = (idx & 7) * 8;
            CP16(smem_u32(&Vs[0][key][c8]), g_v + ((size_t)(b * NN + k0 + key)) * CC + c8);
        }
        CP_COMMIT();
    }

    for (int t = 0; t < 32; t++) {
        if (t + 1 < 32) {
            int nb = (t + 1) & 1, k0 = (t + 1) * 128;
            CP16(smem_u32(&Ks[nb][tid][0]), g_kb + ((size_t)(b * NN + k0 + tid)) * 8);
            #pragma unroll
            for (int i2 = 0; i2 < 8; i2++) {
                int idx = tid + i2 * 128, key = idx >> 3, c8 = (idx & 7) * 8;
                CP16(smem_u32(&Vs[nb][key][c8]), g_v + ((size_t)(b * NN + k0 + key)) * CC + c8);
            }
            CP_COMMIT();
            asm volatile("cp.async.wait_group 1;" ::: "memory");
        } else {
            asm volatile("cp.async.wait_group 0;" ::: "memory");
        }
        __syncthreads();
        int bs = t & 1;

        for (int kc = 0; kc < 8; kc++) {
            uint32_t kb0, kb1;
            {
                uint32_t addr = smem_u32(&Ks[bs][kc * 16 + (lane & 15)][0]);
                asm volatile("ldmatrix.sync.aligned.m8n8.x2.shared.b16 {%0,%1}, [%2];"
                             : "=r"(kb0), "=r"(kb1) : "r"(addr));
            }
            uint32_t vb[8][2];
            #pragma unroll
            for (int m = 0; m < 4; m++) {
                uint32_t addr = smem_u32(&Vs[bs][kc * 16 + (lane & 15)][(lane >> 4) * 8 + m * 16]);
                asm volatile("ldmatrix.sync.aligned.m8n8.x4.trans.shared.b16 {%0,%1,%2,%3}, [%4];"
                             : "=r"(vb[2 * m][0]), "=r"(vb[2 * m][1]),
                               "=r"(vb[2 * m + 1][0]), "=r"(vb[2 * m + 1][1])
                             : "r"(addr));
            }
            #pragma unroll
            for (int i = 0; i < 2; i++) {
                float s0[4] = {0.f, 0.f, 0.f, 0.f}, s1[4] = {0.f, 0.f, 0.f, 0.f};
                MMA_BF16_K8(s0, qa[i][0], qa[i][1], kb0);
                MMA_BF16_K8(s1, qa[i][0], qa[i][1], kb1);
                uint32_t pa0, pa1, pa2, pa3;
                asm("cvt.rn.f16x2.f32 %0, %1, %2;" : "=r"(pa0) : "f"(s0[1]), "f"(s0[0]));
                asm("cvt.rn.f16x2.f32 %0, %1, %2;" : "=r"(pa1) : "f"(s0[3]), "f"(s0[2]));
                asm("cvt.rn.f16x2.f32 %0, %1, %2;" : "=r"(pa2) : "f"(s1[1]), "f"(s1[0]));
                asm("cvt.rn.f16x2.f32 %0, %1, %2;" : "=r"(pa3) : "f"(s1[3]), "f"(s1[2]));
                asm("ex2.approx.f16x2 %0, %0;" : "+r"(pa0));
                asm("ex2.approx.f16x2 %0, %0;" : "+r"(pa1));
                asm("ex2.approx.f16x2 %0, %0;" : "+r"(pa2));
                asm("ex2.approx.f16x2 %0, %0;" : "+r"(pa3));
                uint32_t h0, h1;
                asm("add.rn.f16x2 %0, %1, %2;" : "=r"(h0) : "r"(pa0), "r"(pa2));
                asm("add.rn.f16x2 %0, %1, %2;" : "=r"(h1) : "r"(pa1), "r"(pa3));
                float2 f0 = __half22float2(*reinterpret_cast<__half2*>(&h0));
                float2 f1 = __half22float2(*reinterpret_cast<__half2*>(&h1));
                lrow[2 * i]     += f0.x + f0.y;
                lrow[2 * i + 1] += f1.x + f1.y;
                #pragma unroll
                for (int j = 0; j < 8; j++)
                    MMA_F16(d2[i][j], pa0, pa1, pa2, pa3, vb[j][0], vb[j][1]);
            }
        }
        __syncthreads();
    }

    #pragma unroll
    for (int r = 0; r < 4; r++) {
        lrow[r] += __shfl_xor_sync(0xffffffffu, lrow[r], 1);
        lrow[r] += __shfl_xor_sync(0xffffffffu, lrow[r], 2);
    }
    float gm = gamma[0];
    float inv[4];
    #pragma unroll
    for (int r = 0; r < 4; r++) inv[r] = gm / lrow[r];

    const float* cb = cnn + (size_t)b * CC * NN;
    float* ob = out + (size_t)b * CC * NN;
    #pragma unroll
    for (int i = 0; i < 2; i++) {
        int q0 = qbase + i * 16 + g;
        #pragma unroll
        for (int j = 0; j < 8; j++) {
            int ch = j * 8 + 2 * tp;
            ob[(size_t)ch * NN + q0]           = d2[i][j][0] * inv[2 * i]     + cb[(size_t)ch * NN + q0];
            ob[(size_t)(ch + 1) * NN + q0]     = d2[i][j][1] * inv[2 * i]     + cb[(size_t)(ch + 1) * NN + q0];
            ob[(size_t)ch * NN + q0 + 8]       = d2[i][j][2] * inv[2 * i + 1] + cb[(size_t)ch * NN + q0 + 8];
            ob[(size_t)(ch + 1) * NN + q0 + 8] = d2[i][j][3] * inv[2 * i + 1] + cb[(size_t)(ch + 1) * NN + q0 + 8];
        }
    }
}

// ---------------- launch ---------------------------------------------------------
extern "C" void kernel_launch(void* const* d_in, const int* in_sizes, int n_in,
                              void* d_out, int out_size) {
    const float* cnn   = (const float*)d_in[0];
    const float* vit   = (const float*)d_in[1];
    const float* Wq    = (const float*)d_in[2];
    const float* bq    = (const float*)d_in[3];
    const float* Wk    = (const float*)d_in[4];
    const float* bk    = (const float*)d_in[5];
    const float* Wv    = (const float*)d_in[6];
    const float* bv    = (const float*)d_in[7];
    const float* gamma = (const float*)d_in[8];
    const float* gcnn  = (const float*)d_in[9];
    const float* gvit  = (const float*)d_in[10];
    float* out = (float*)d_out;

    k_gram  <<<dim3(NCHUNK, NIMG), 256>>>(cnn, vit);
    k_prep  <<<NIMG, 256>>>(Wq, Wk, Wv, gcnn, gvit);
    k_qk    <<<dim3(NN / 128, BB, 2), 128>>>(cnn, vit, bq, bk);
    k_vproj <<<dim3(NN / 64, BB), 256>>>(vit, bv);
    k_attn  <<<dim3(NN / 128, BB), 128>>>(gamma, cnn, out);
}

// round 6
// speedup vs baseline: 4.5380x; 1.2422x over previous
#include <cuda_runtime.h>
#include <cuda_bf16.h>
#include <cuda_fp16.h>
#include <cstdint>

// Problem constants
#define BB 4
#define CC 64
#define NN 4096
#define C8V 8
#define NIMG 8
#define NCHUNK 32
#define RLN2 1.4426950408889634f

// ---------------- scratch ----------------------------------------------------
__device__ float g_gpart[NCHUNK * NIMG * CC * CC];
__device__ float g_WqT[BB * CC * C8V];             // [b][c][o], prescaled by 1/ln2
__device__ float g_WkT[BB * CC * C8V];             // [b][c][o]
__device__ float g_WvTe[BB * CC * CC];             // [b][c][o]
__device__ __nv_bfloat16 g_qb[BB * NN * C8V];      // [b][n][8] (prescaled 1/ln2)
__device__ __nv_bfloat16 g_kb[BB * NN * C8V];      // [b][n][8]
__device__ __half        g_v [BB * NN * CC];       // [b][n][c]

__device__ __forceinline__ uint32_t smem_u32(const void* p) {
    uint32_t a;
    asm("{ .reg .u64 t; cvta.to.shared.u64 t, %1; cvt.u32.u64 %0, t; }" : "=r"(a) : "l"(p));
    return a;
}

#define MMA_BF16_K8(d, a0, a1, b0)                                                 \
    asm volatile("mma.sync.aligned.m16n8k8.row.col.f32.bf16.bf16.f32 "             \
        "{%0,%1,%2,%3}, {%4,%5}, {%6}, {%0,%1,%2,%3};"                             \
        : "+f"((d)[0]), "+f"((d)[1]), "+f"((d)[2]), "+f"((d)[3])                   \
        : "r"(a0), "r"(a1), "r"(b0))

#define MMA_F16(d, a0, a1, a2, a3, b0, b1)                                         \
    asm volatile("mma.sync.aligned.m16n8k16.row.col.f32.f16.f16.f32 "              \
        "{%0,%1,%2,%3}, {%4,%5,%6,%7}, {%8,%9}, {%0,%1,%2,%3};"                    \
        : "+f"((d)[0]), "+f"((d)[1]), "+f"((d)[2]), "+f"((d)[3])                   \
        : "r"(a0), "r"(a1), "r"(a2), "r"(a3), "r"(b0), "r"(b1))

#define CP16(dst, src) asm volatile("cp.async.cg.shared.global [%0], [%1], 16;" :: "r"(dst), "l"(src) : "memory")
#define CP_COMMIT()    asm volatile("cp.async.commit_group;" ::: "memory")

// ---------------- Stage A1: gram partials (4x4 register tiles) -----------------
__global__ void k_gram(const float* __restrict__ cnn, const float* __restrict__ vit) {
    int chunk = blockIdx.x, img = blockIdx.y;
    const float* x = (img < BB) ? (cnn + img * CC * NN) : (vit + (img - BB) * CC * NN);
    __shared__ float xs[CC][132];
    int n0 = chunk * 128;
    for (int i = threadIdx.x; i < CC * 128; i += 256) {
        int c = i >> 7, j = i & 127;
        xs[c][j] = x[c * NN + n0 + j];
    }
    __syncthreads();
    int tx = threadIdx.x & 15, ty = threadIdx.x >> 4;
    int ci0 = ty * 4, cj0 = tx * 4;
    float acc[4][4];
    #pragma unroll
    for (int i = 0; i < 4; i++)
        #pragma unroll
        for (int j = 0; j < 4; j++) acc[i][j] = 0.f;
    for (int j = 0; j < 128; j += 4) {
        float4 a[4], bvv[4];
        #pragma unroll
        for (int i = 0; i < 4; i++) a[i] = *(const float4*)&xs[ci0 + i][j];
        #pragma unroll
        for (int i = 0; i < 4; i++) bvv[i] = *(const float4*)&xs[cj0 + i][j];
        #pragma unroll
        for (int i = 0; i < 4; i++)
            #pragma unroll
            for (int jj = 0; jj < 4; jj++)
                acc[i][jj] += a[i].x * bvv[jj].x + a[i].y * bvv[jj].y
                            + a[i].z * bvv[jj].z + a[i].w * bvv[jj].w;
    }
    float* outp = g_gpart + (chunk * NIMG + img) * CC * CC;
    #pragma unroll
    for (int i = 0; i < 4; i++)
        *(float4*)&outp[(ci0 + i) * CC + cj0] =
            make_float4(acc[i][0], acc[i][1], acc[i][2], acc[i][3]);
}

// ---------------- Stage A2: reduce + softmax + effective-weight compose --------
__global__ void k_prep(const float* __restrict__ Wq, const float* __restrict__ Wk,
                       const float* __restrict__ Wv,
                       const float* __restrict__ gcnn, const float* __restrict__ gvit) {
    int img = blockIdx.x;
    int tid = threadIdx.x;
    __shared__ __align__(16) float As[CC * CC];
    __shared__ __align__(16) float Wvs[CC * 68];
    __shared__ float Wqs[CC * C8V];

    for (int p = tid; p < CC * CC; p += 256) {
        float s = 0.f;
        #pragma unroll
        for (int ch = 0; ch < NCHUNK; ch++)
            s += g_gpart[(ch * NIMG + img) * CC * CC + p];
        As[p] = s;
    }
    __syncthreads();

    {
        int r = tid >> 2, l4 = tid & 3;
        float m = -1e30f;
        for (int d = l4; d < CC; d += 4) m = fmaxf(m, -As[r * CC + d]);
        m = fmaxf(m, __shfl_xor_sync(0xffffffffu, m, 1));
        m = fmaxf(m, __shfl_xor_sync(0xffffffffu, m, 2));
        float s = 0.f;
        for (int d = l4; d < CC; d += 4) s += __expf(-As[r * CC + d] - m);
        s += __shfl_xor_sync(0xffffffffu, s, 1);
        s += __shfl_xor_sync(0xffffffffu, s, 2);
        float inv = 1.f / s;
        for (int d = l4; d < CC; d += 4)
            As[r * CC + d] = __expf(-As[r * CC + d] - m) * inv;
    }

    const float* Wsm = (img < BB) ? Wq : Wk;
    for (int i = tid; i < C8V * CC; i += 256)
        Wqs[(i & 63) * C8V + (i >> 6)] = Wsm[i];
    if (img >= BB) {
        for (int i = tid; i < CC * CC; i += 256)
            Wvs[(i & 63) * 68 + (i >> 6)] = Wv[i];
    }
    __syncthreads();

    if (img < BB) {
        float g = gcnn[0];
        for (int p = tid; p < CC * C8V; p += 256) {
            int d = p >> 3, o = p & 7;
            float s = 0.f;
            #pragma unroll 4
            for (int c = 0; c < CC; c++) s += Wqs[c * C8V + o] * As[c * CC + d];
            g_WqT[img * CC * C8V + d * C8V + o] = (Wqs[d * C8V + o] + g * s) * RLN2;
        }
    } else {
        int b = img - BB;
        float g = gvit[0];
        for (int p = tid; p < CC * C8V; p += 256) {
            int d = p >> 3, o = p & 7;
            float s = 0.f;
            #pragma unroll 4
            for (int c = 0; c < CC; c++) s += Wqs[c * C8V + o] * As[c * CC + d];
            g_WkT[b * CC * C8V + d * C8V + o] = Wqs[d * C8V + o] + g * s;
        }
        int tx = tid & 15, ty = tid >> 4;
        int o0 = tx * 4, d0 = ty * 4;
        float acc[4][4];
        #pragma unroll
        for (int i = 0; i < 4; i++)
            #pragma unroll
            for (int j = 0; j < 4; j++) acc[i][j] = 0.f;
        for (int c = 0; c < CC; c++) {
            float4 a = *(const float4*)&As[c * CC + d0];
            float4 wv = *(const float4*)&Wvs[c * 68 + o0];
            float ar[4] = {a.x, a.y, a.z, a.w};
            float wr[4] = {wv.x, wv.y, wv.z, wv.w};
            #pragma unroll
            for (int i = 0; i < 4; i++)
                #pragma unroll
                for (int j = 0; j < 4; j++) acc[i][j] += ar[i] * wr[j];
        }
        #pragma unroll
        for (int i = 0; i < 4; i++) {
            float4 wd = *(const float4*)&Wvs[(d0 + i) * 68 + o0];
            float4 o = make_float4(wd.x + g * acc[i][0], wd.y + g * acc[i][1],
                                   wd.z + g * acc[i][2], wd.w + g * acc[i][3]);
            *(float4*)&g_WvTe[b * CC * CC + (d0 + i) * CC + o0] = o;
        }
    }
}

// ---------------- Stage B: fused q/k/v projections ------------------------------
// grid (NN/32, BB), 192 threads (6 warps): warps 0-3 -> v (16ch each),
// warp 4 -> q, warp 5 -> k. Weights staged in smem (broadcast LDS).
__global__ void __launch_bounds__(192) k_qkv(const float* __restrict__ cnn,
                                             const float* __restrict__ vit,
                                             const float* __restrict__ bq,
                                             const float* __restrict__ bk,
                                             const float* __restrict__ bv) {
    int n0 = blockIdx.x * 32, b = blockIdx.y;
    int tid = threadIdx.x, ww = tid >> 5, lane = tid & 31;
    int n = n0 + lane;

    __shared__ __align__(16) float Wvs[CC * CC];   // [c][o]
    __shared__ __align__(16) float Wqs[CC * C8V];
    __shared__ __align__(16) float Wks[CC * C8V];

    const float* wsrc = g_WvTe + b * CC * CC;
    for (int i = tid; i < CC * CC / 4; i += 192)
        *(float4*)&Wvs[i * 4] = *(const float4*)&wsrc[i * 4];
    if (tid < 128) {
        *(float4*)&Wqs[tid * 4] = *(const float4*)&g_WqT[b * CC * C8V + tid * 4];
        *(float4*)&Wks[tid * 4] = *(const float4*)&g_WkT[b * CC * C8V + tid * 4];
    }
    __syncthreads();

    if (ww < 4) {
        int og = ww * 16;
        const float* src = vit + (size_t)b * CC * NN;
        float acc[16];
        #pragma unroll
        for (int i = 0; i < 16; i++) acc[i] = bv[og + i];
        #pragma unroll 4
        for (int c = 0; c < CC; c++) {
            float xv = src[c * NN + n];
            #pragma unroll
            for (int m = 0; m < 4; m++) {
                float4 w = *(const float4*)&Wvs[c * CC + og + m * 4];
                acc[m * 4 + 0] += w.x * xv; acc[m * 4 + 1] += w.y * xv;
                acc[m * 4 + 2] += w.z * xv; acc[m * 4 + 3] += w.w * xv;
            }
        }
        __half* dst = g_v + ((size_t)(b * NN + n)) * CC + og;
        #pragma unroll
        for (int m = 0; m < 4; m++) {
            ushort4 u;
            u.x = __half_as_ushort(__float2half(acc[m * 4 + 0]));
            u.y = __half_as_ushort(__float2half(acc[m * 4 + 1]));
            u.z = __half_as_ushort(__float2half(acc[m * 4 + 2]));
            u.w = __half_as_ushort(__float2half(acc[m * 4 + 3]));
            *(ushort4*)(dst + m * 4) = u;
        }
    } else {
        bool isQ = (ww == 4);
        const float* src = (isQ ? cnn : vit) + (size_t)b * CC * NN;
        const float* Ws = isQ ? Wqs : Wks;
        const float* bias = isQ ? bq : bk;
        float bscale = isQ ? RLN2 : 1.0f;
        __nv_bfloat16* dst = isQ ? g_qb : g_kb;
        float acc[8];
        #pragma unroll
        for (int o = 0; o < 8; o++) acc[o] = bias[o] * bscale;
        #pragma unroll 8
        for (int c = 0; c < CC; c++) {
            float xv = src[c * NN + n];
            float4 w0 = *(const float4*)&Ws[c * C8V];
            float4 w1 = *(const float4*)&Ws[c * C8V + 4];
            acc[0] += w0.x * xv; acc[1] += w0.y * xv; acc[2] += w0.z * xv; acc[3] += w0.w * xv;
            acc[4] += w1.x * xv; acc[5] += w1.y * xv; acc[6] += w1.z * xv; acc[7] += w1.w * xv;
        }
        ushort4 u0, u1;
        u0.x = __bfloat16_as_ushort(__float2bfloat16(acc[0]));
        u0.y = __bfloat16_as_ushort(__float2bfloat16(acc[1]));
        u0.z = __bfloat16_as_ushort(__float2bfloat16(acc[2]));
        u0.w = __bfloat16_as_ushort(__float2bfloat16(acc[3]));
        u1.x = __bfloat16_as_ushort(__float2bfloat16(acc[4]));
        u1.y = __bfloat16_as_ushort(__float2bfloat16(acc[5]));
        u1.z = __bfloat16_as_ushort(__float2bfloat16(acc[6]));
        u1.w = __bfloat16_as_ushort(__float2bfloat16(acc[7]));
        *(ushort4*)(dst + ((size_t)(b * NN + n)) * 8)     = u0;
        *(ushort4*)(dst + ((size_t)(b * NN + n)) * 8 + 4) = u1;
    }
}

// ---------------- Stage C: mma attention, 8 warps, cp.async pipelined ----------
__global__ void __launch_bounds__(256) k_attn(const float* __restrict__ gamma,
                                              const float* __restrict__ cnn,
                                              float* __restrict__ out) {
    int qt = blockIdx.x, b = blockIdx.y;
    int tid = threadIdx.x;
    int w = tid >> 5, lane = tid & 31;
    int g = lane >> 2, tp = lane & 3;

    __shared__ __align__(16) __nv_bfloat16 Ks[2][128][8];
    __shared__ __align__(16) __half        Vs[2][128][72];

    int qbase = qt * 128 + w * 16;
    uint32_t qa0 = *(const uint32_t*)(g_qb + ((size_t)(b * NN + qbase + g)) * 8 + 2 * tp);
    uint32_t qa1 = *(const uint32_t*)(g_qb + ((size_t)(b * NN + qbase + g + 8)) * 8 + 2 * tp);

    float d2[8][4];
    #pragma unroll
    for (int j = 0; j < 8; j++)
        #pragma unroll
        for (int r = 0; r < 4; r++) d2[j][r] = 0.f;
    float lrow[2] = {0.f, 0.f};

    {
        if (tid < 128) CP16(smem_u32(&Ks[0][tid][0]), g_kb + ((size_t)(b * NN + tid)) * 8);
        #pragma unroll
        for (int i2 = 0; i2 < 4; i2++) {
            int idx = tid + i2 * 256, key = idx >> 3, c8 = (idx & 7) * 8;
            CP16(smem_u32(&Vs[0][key][c8]), g_v + ((size_t)(b * NN + key)) * CC + c8);
        }
        CP_COMMIT();
    }

    for (int t = 0; t < 32; t++) {
        if (t + 1 < 32) {
            int nb = (t + 1) & 1, k0 = (t + 1) * 128;
            if (tid < 128) CP16(smem_u32(&Ks[nb][tid][0]), g_kb + ((size_t)(b * NN + k0 + tid)) * 8);
            #pragma unroll
            for (int i2 = 0; i2 < 4; i2++) {
                int idx = tid + i2 * 256, key = idx >> 3, c8 = (idx & 7) * 8;
                CP16(smem_u32(&Vs[nb][key][c8]), g_v + ((size_t)(b * NN + k0 + key)) * CC + c8);
            }
            CP_COMMIT();
            asm volatile("cp.async.wait_group 1;" ::: "memory");
        } else {
            asm volatile("cp.async.wait_group 0;" ::: "memory");
        }
        __syncthreads();
        int bs = t & 1;

        for (int kc = 0; kc < 8; kc++) {
            uint32_t kb0, kb1;
            {
                uint32_t addr = smem_u32(&Ks[bs][kc * 16 + (lane & 15)][0]);
                asm volatile("ldmatrix.sync.aligned.m8n8.x2.shared.b16 {%0,%1}, [%2];"
                             : "=r"(kb0), "=r"(kb1) : "r"(addr));
            }
            uint32_t vb[8][2];
            #pragma unroll
            for (int m = 0; m < 4; m++) {
                uint32_t addr = smem_u32(&Vs[bs][kc * 16 + (lane & 15)][(lane >> 4) * 8 + m * 16]);
                asm volatile("ldmatrix.sync.aligned.m8n8.x4.trans.shared.b16 {%0,%1,%2,%3}, [%4];"
                             : "=r"(vb[2 * m][0]), "=r"(vb[2 * m][1]),
                               "=r"(vb[2 * m + 1][0]), "=r"(vb[2 * m + 1][1])
                             : "r"(addr));
            }
            float s0[4] = {0.f, 0.f, 0.f, 0.f}, s1[4] = {0.f, 0.f, 0.f, 0.f};
            MMA_BF16_K8(s0, qa0, qa1, kb0);
            MMA_BF16_K8(s1, qa0, qa1, kb1);
            uint32_t pa0, pa1, pa2, pa3;
            asm("cvt.rn.f16x2.f32 %0, %1, %2;" : "=r"(pa0) : "f"(s0[1]), "f"(s0[0]));
            asm("cvt.rn.f16x2.f32 %0, %1, %2;" : "=r"(pa1) : "f"(s0[3]), "f"(s0[2]));
            asm("cvt.rn.f16x2.f32 %0, %1, %2;" : "=r"(pa2) : "f"(s1[1]), "f"(s1[0]));
            asm("cvt.rn.f16x2.f32 %0, %1, %2;" : "=r"(pa3) : "f"(s1[3]), "f"(s1[2]));
            asm("ex2.approx.f16x2 %0, %0;" : "+r"(pa0));
            asm("ex2.approx.f16x2 %0, %0;" : "+r"(pa1));
            asm("ex2.approx.f16x2 %0, %0;" : "+r"(pa2));
            asm("ex2.approx.f16x2 %0, %0;" : "+r"(pa3));
            uint32_t h0, h1;
            asm("add.rn.f16x2 %0, %1, %2;" : "=r"(h0) : "r"(pa0), "r"(pa2));
            asm("add.rn.f16x2 %0, %1, %2;" : "=r"(h1) : "r"(pa1), "r"(pa3));
            float2 f0 = __half22float2(*reinterpret_cast<__half2*>(&h0));
            float2 f1 = __half22float2(*reinterpret_cast<__half2*>(&h1));
            lrow[0] += f0.x + f0.y;
            lrow[1] += f1.x + f1.y;
            #pragma unroll
            for (int j = 0; j < 8; j++)
                MMA_F16(d2[j], pa0, pa1, pa2, pa3, vb[j][0], vb[j][1]);
        }
        __syncthreads();
    }

    #pragma unroll
    for (int r = 0; r < 2; r++) {
        lrow[r] += __shfl_xor_sync(0xffffffffu, lrow[r], 1);
        lrow[r] += __shfl_xor_sync(0xffffffffu, lrow[r], 2);
    }
    float gm = gamma[0];
    float inv0 = gm / lrow[0], inv1 = gm / lrow[1];

    const float* cb = cnn + (size_t)b * CC * NN;
    float* ob = out + (size_t)b * CC * NN;
    int q0 = qbase + g, q1 = qbase + g + 8;
    #pragma unroll
    for (int j = 0; j < 8; j++) {
        int ch = j * 8 + 2 * tp;
        ob[(size_t)ch * NN + q0]       = d2[j][0] * inv0 + cb[(size_t)ch * NN + q0];
        ob[(size_t)(ch + 1) * NN + q0] = d2[j][1] * inv0 + cb[(size_t)(ch + 1) * NN + q0];
        ob[(size_t)ch * NN + q1]       = d2[j][2] * inv1 + cb[(size_t)ch * NN + q1];
        ob[(size_t)(ch + 1) * NN + q1] = d2[j][3] * inv1 + cb[(size_t)(ch + 1) * NN + q1];
    }
}

// ---------------- launch ---------------------------------------------------------
extern "C" void kernel_launch(void* const* d_in, const int* in_sizes, int n_in,
                              void* d_out, int out_size) {
    const float* cnn   = (const float*)d_in[0];
    const float* vit   = (const float*)d_in[1];
    const float* Wq    = (const float*)d_in[2];
    const float* bq    = (const float*)d_in[3];
    const float* Wk    = (const float*)d_in[4];
    const float* bk    = (const float*)d_in[5];
    const float* Wv    = (const float*)d_in[6];
    const float* bv    = (const float*)d_in[7];
    const float* gamma = (const float*)d_in[8];
    const float* gcnn  = (const float*)d_in[9];
    const float* gvit  = (const float*)d_in[10];
    float* out = (float*)d_out;

    k_gram <<<dim3(NCHUNK, NIMG), 256>>>(cnn, vit);
    k_prep <<<NIMG, 256>>>(Wq, Wk, Wv, gcnn, gvit);
    k_qkv  <<<dim3(NN / 32, BB), 192>>>(cnn, vit, bq, bk, bv);
    k_attn <<<dim3(NN / 128, BB), 256>>>(gamma, cnn, out);
}

// round 7
// speedup vs baseline: 4.8700x; 1.0732x over previous
#include <cuda_runtime.h>
#include <cuda_bf16.h>
#include <cuda_fp16.h>
#include <cstdint>

// Problem constants
#define BB 4
#define CC 64
#define NN 4096
#define C8V 8
#define NIMG 8
#define NCHUNK 32
#define KSPL 2
#define RLN2 1.4426950408889634f

// ---------------- scratch ----------------------------------------------------
__device__ float g_gpart[NCHUNK * NIMG * CC * CC];
__device__ float g_WqT[BB * CC * C8V];             // [b][c][o], prescaled by 1/ln2
__device__ float g_WkT[BB * CC * C8V];             // [b][c][o]
__device__ float g_WvTe[BB * CC * CC];             // [b][c][o]
__device__ __nv_bfloat16 g_qb[BB * NN * C8V];      // [b][n][8] (prescaled 1/ln2)
__device__ __nv_bfloat16 g_kb[BB * NN * C8V];      // [b][n][8]
__device__ __half        g_v [BB * NN * CC];       // [b][n][c]
__device__ float g_pD[BB * KSPL * CC * NN];        // attention partial D [b][s][c][q]
__device__ float g_pl[BB * KSPL * NN];             // attention partial l [b][s][q]

__device__ __forceinline__ uint32_t smem_u32(const void* p) {
    uint32_t a;
    asm("{ .reg .u64 t; cvta.to.shared.u64 t, %1; cvt.u32.u64 %0, t; }" : "=r"(a) : "l"(p));
    return a;
}

#define MMA_BF16_K8(d, a0, a1, b0)                                                 \
    asm volatile("mma.sync.aligned.m16n8k8.row.col.f32.bf16.bf16.f32 "             \
        "{%0,%1,%2,%3}, {%4,%5}, {%6}, {%0,%1,%2,%3};"                             \
        : "+f"((d)[0]), "+f"((d)[1]), "+f"((d)[2]), "+f"((d)[3])                   \
        : "r"(a0), "r"(a1), "r"(b0))

#define MMA_F16(d, a0, a1, a2, a3, b0, b1)                                         \
    asm volatile("mma.sync.aligned.m16n8k16.row.col.f32.f16.f16.f32 "              \
        "{%0,%1,%2,%3}, {%4,%5,%6,%7}, {%8,%9}, {%0,%1,%2,%3};"                    \
        : "+f"((d)[0]), "+f"((d)[1]), "+f"((d)[2]), "+f"((d)[3])                   \
        : "r"(a0), "r"(a1), "r"(a2), "r"(a3), "r"(b0), "r"(b1))

#define CP16(dst, src) asm volatile("cp.async.cg.shared.global [%0], [%1], 16;" :: "r"(dst), "l"(src) : "memory")
#define CP_COMMIT()    asm volatile("cp.async.commit_group;" ::: "memory")

// ---------------- Stage A1: gram partials (4x4 register tiles) -----------------
__global__ void k_gram(const float* __restrict__ cnn, const float* __restrict__ vit) {
    int chunk = blockIdx.x, img = blockIdx.y;
    const float* x = (img < BB) ? (cnn + img * CC * NN) : (vit + (img - BB) * CC * NN);
    __shared__ float xs[CC][132];
    int n0 = chunk * 128;
    for (int i = threadIdx.x; i < CC * 128; i += 256) {
        int c = i >> 7, j = i & 127;
        xs[c][j] = x[c * NN + n0 + j];
    }
    __syncthreads();
    int tx = threadIdx.x & 15, ty = threadIdx.x >> 4;
    int ci0 = ty * 4, cj0 = tx * 4;
    float acc[4][4];
    #pragma unroll
    for (int i = 0; i < 4; i++)
        #pragma unroll
        for (int j = 0; j < 4; j++) acc[i][j] = 0.f;
    for (int j = 0; j < 128; j += 4) {
        float4 a[4], bvv[4];
        #pragma unroll
        for (int i = 0; i < 4; i++) a[i] = *(const float4*)&xs[ci0 + i][j];
        #pragma unroll
        for (int i = 0; i < 4; i++) bvv[i] = *(const float4*)&xs[cj0 + i][j];
        #pragma unroll
        for (int i = 0; i < 4; i++)
            #pragma unroll
            for (int jj = 0; jj < 4; jj++)
                acc[i][jj] += a[i].x * bvv[jj].x + a[i].y * bvv[jj].y
                            + a[i].z * bvv[jj].z + a[i].w * bvv[jj].w;
    }
    float* outp = g_gpart + (chunk * NIMG + img) * CC * CC;
    #pragma unroll
    for (int i = 0; i < 4; i++)
        *(float4*)&outp[(ci0 + i) * CC + cj0] =
            make_float4(acc[i][0], acc[i][1], acc[i][2], acc[i][3]);
}

// ---------------- Stage A2: reduce + softmax + effective-weight compose --------
__global__ void k_prep(const float* __restrict__ Wq, const float* __restrict__ Wk,
                       const float* __restrict__ Wv,
                       const float* __restrict__ gcnn, const float* __restrict__ gvit) {
    int img = blockIdx.x;
    int tid = threadIdx.x;
    __shared__ __align__(16) float As[CC * CC];
    __shared__ __align__(16) float Wvs[CC * 68];
    __shared__ float Wqs[CC * C8V];

    for (int p = tid; p < CC * CC; p += 256) {
        float s = 0.f;
        #pragma unroll
        for (int ch = 0; ch < NCHUNK; ch++)
            s += g_gpart[(ch * NIMG + img) * CC * CC + p];
        As[p] = s;
    }
    __syncthreads();

    {
        int r = tid >> 2, l4 = tid & 3;
        float m = -1e30f;
        for (int d = l4; d < CC; d += 4) m = fmaxf(m, -As[r * CC + d]);
        m = fmaxf(m, __shfl_xor_sync(0xffffffffu, m, 1));
        m = fmaxf(m, __shfl_xor_sync(0xffffffffu, m, 2));
        float s = 0.f;
        for (int d = l4; d < CC; d += 4) s += __expf(-As[r * CC + d] - m);
        s += __shfl_xor_sync(0xffffffffu, s, 1);
        s += __shfl_xor_sync(0xffffffffu, s, 2);
        float inv = 1.f / s;
        for (int d = l4; d < CC; d += 4)
            As[r * CC + d] = __expf(-As[r * CC + d] - m) * inv;
    }

    const float* Wsm = (img < BB) ? Wq : Wk;
    for (int i = tid; i < C8V * CC; i += 256)
        Wqs[(i & 63) * C8V + (i >> 6)] = Wsm[i];
    if (img >= BB) {
        for (int i = tid; i < CC * CC; i += 256)
            Wvs[(i & 63) * 68 + (i >> 6)] = Wv[i];
    }
    __syncthreads();

    if (img < BB) {
        float g = gcnn[0];
        for (int p = tid; p < CC * C8V; p += 256) {
            int d = p >> 3, o = p & 7;
            float s = 0.f;
            #pragma unroll 4
            for (int c = 0; c < CC; c++) s += Wqs[c * C8V + o] * As[c * CC + d];
            g_WqT[img * CC * C8V + d * C8V + o] = (Wqs[d * C8V + o] + g * s) * RLN2;
        }
    } else {
        int b = img - BB;
        float g = gvit[0];
        for (int p = tid; p < CC * C8V; p += 256) {
            int d = p >> 3, o = p & 7;
            float s = 0.f;
            #pragma unroll 4
            for (int c = 0; c < CC; c++) s += Wqs[c * C8V + o] * As[c * CC + d];
            g_WkT[b * CC * C8V + d * C8V + o] = Wqs[d * C8V + o] + g * s;
        }
        int tx = tid & 15, ty = tid >> 4;
        int o0 = tx * 4, d0 = ty * 4;
        float acc[4][4];
        #pragma unroll
        for (int i = 0; i < 4; i++)
            #pragma unroll
            for (int j = 0; j < 4; j++) acc[i][j] = 0.f;
        for (int c = 0; c < CC; c++) {
            float4 a = *(const float4*)&As[c * CC + d0];
            float4 wv = *(const float4*)&Wvs[c * 68 + o0];
            float ar[4] = {a.x, a.y, a.z, a.w};
            float wr[4] = {wv.x, wv.y, wv.z, wv.w};
            #pragma unroll
            for (int i = 0; i < 4; i++)
                #pragma unroll
                for (int j = 0; j < 4; j++) acc[i][j] += ar[i] * wr[j];
        }
        #pragma unroll
        for (int i = 0; i < 4; i++) {
            float4 wd = *(const float4*)&Wvs[(d0 + i) * 68 + o0];
            float4 o = make_float4(wd.x + g * acc[i][0], wd.y + g * acc[i][1],
                                   wd.z + g * acc[i][2], wd.w + g * acc[i][3]);
            *(float4*)&g_WvTe[b * CC * CC + (d0 + i) * CC + o0] = o;
        }
    }
}

// ---------------- Stage B: fused q/k/v projections ------------------------------
__global__ void __launch_bounds__(192) k_qkv(const float* __restrict__ cnn,
                                             const float* __restrict__ vit,
                                             const float* __restrict__ bq,
                                             const float* __restrict__ bk,
                                             const float* __restrict__ bv) {
    int n0 = blockIdx.x * 32, b = blockIdx.y;
    int tid = threadIdx.x, ww = tid >> 5, lane = tid & 31;
    int n = n0 + lane;

    __shared__ __align__(16) float Wvs[CC * CC];
    __shared__ __align__(16) float Wqs[CC * C8V];
    __shared__ __align__(16) float Wks[CC * C8V];

    const float* wsrc = g_WvTe + b * CC * CC;
    for (int i = tid; i < CC * CC / 4; i += 192)
        *(float4*)&Wvs[i * 4] = *(const float4*)&wsrc[i * 4];
    if (tid < 128) {
        *(float4*)&Wqs[tid * 4] = *(const float4*)&g_WqT[b * CC * C8V + tid * 4];
        *(float4*)&Wks[tid * 4] = *(const float4*)&g_WkT[b * CC * C8V + tid * 4];
    }
    __syncthreads();

    if (ww < 4) {
        int og = ww * 16;
        const float* src = vit + (size_t)b * CC * NN;
        float acc[16];
        #pragma unroll
        for (int i = 0; i < 16; i++) acc[i] = bv[og + i];
        #pragma unroll 4
        for (int c = 0; c < CC; c++) {
            float xv = src[c * NN + n];
            #pragma unroll
            for (int m = 0; m < 4; m++) {
                float4 w = *(const float4*)&Wvs[c * CC + og + m * 4];
                acc[m * 4 + 0] += w.x * xv; acc[m * 4 + 1] += w.y * xv;
                acc[m * 4 + 2] += w.z * xv; acc[m * 4 + 3] += w.w * xv;
            }
        }
        __half* dst = g_v + ((size_t)(b * NN + n)) * CC + og;
        #pragma unroll
        for (int m = 0; m < 4; m++) {
            ushort4 u;
            u.x = __half_as_ushort(__float2half(acc[m * 4 + 0]));
            u.y = __half_as_ushort(__float2half(acc[m * 4 + 1]));
            u.z = __half_as_ushort(__float2half(acc[m * 4 + 2]));
            u.w = __half_as_ushort(__float2half(acc[m * 4 + 3]));
            *(ushort4*)(dst + m * 4) = u;
        }
    } else {
        bool isQ = (ww == 4);
        const float* src = (isQ ? cnn : vit) + (size_t)b * CC * NN;
        const float* Ws = isQ ? Wqs : Wks;
        const float* bias = isQ ? bq : bk;
        float bscale = isQ ? RLN2 : 1.0f;
        __nv_bfloat16* dst = isQ ? g_qb : g_kb;
        float acc[8];
        #pragma unroll
        for (int o = 0; o < 8; o++) acc[o] = bias[o] * bscale;
        #pragma unroll 8
        for (int c = 0; c < CC; c++) {
            float xv = src[c * NN + n];
            float4 w0 = *(const float4*)&Ws[c * C8V];
            float4 w1 = *(const float4*)&Ws[c * C8V + 4];
            acc[0] += w0.x * xv; acc[1] += w0.y * xv; acc[2] += w0.z * xv; acc[3] += w0.w * xv;
            acc[4] += w1.x * xv; acc[5] += w1.y * xv; acc[6] += w1.z * xv; acc[7] += w1.w * xv;
        }
        ushort4 u0, u1;
        u0.x = __bfloat16_as_ushort(__float2bfloat16(acc[0]));
        u0.y = __bfloat16_as_ushort(__float2bfloat16(acc[1]));
        u0.z = __bfloat16_as_ushort(__float2bfloat16(acc[2]));
        u0.w = __bfloat16_as_ushort(__float2bfloat16(acc[3]));
        u1.x = __bfloat16_as_ushort(__float2bfloat16(acc[4]));
        u1.y = __bfloat16_as_ushort(__float2bfloat16(acc[5]));
        u1.z = __bfloat16_as_ushort(__float2bfloat16(acc[6]));
        u1.w = __bfloat16_as_ushort(__float2bfloat16(acc[7]));
        *(ushort4*)(dst + ((size_t)(b * NN + n)) * 8)     = u0;
        *(ushort4*)(dst + ((size_t)(b * NN + n)) * 8 + 4) = u1;
    }
}

// ---------------- Stage C: mma attention, key-split, cp.async pipelined --------
// grid (32, 4, KSPL), 256 threads (8 warps, 16 q rows each). Partial outputs.
#define NTILE (NN / KSPL / 128)
__global__ void __launch_bounds__(256) k_attn() {
    int qt = blockIdx.x, b = blockIdx.y, sp = blockIdx.z;
    int tid = threadIdx.x;
    int w = tid >> 5, lane = tid & 31;
    int g = lane >> 2, tp = lane & 3;
    int kbase = sp * (NN / KSPL);

    __shared__ __align__(16) __nv_bfloat16 Ks[2][128][8];
    __shared__ __align__(16) __half        Vs[2][128][72];

    int qbase = qt * 128 + w * 16;
    uint32_t qa0 = *(const uint32_t*)(g_qb + ((size_t)(b * NN + qbase + g)) * 8 + 2 * tp);
    uint32_t qa1 = *(const uint32_t*)(g_qb + ((size_t)(b * NN + qbase + g + 8)) * 8 + 2 * tp);

    float d2[8][4];
    #pragma unroll
    for (int j = 0; j < 8; j++)
        #pragma unroll
        for (int r = 0; r < 4; r++) d2[j][r] = 0.f;
    float lrow[2] = {0.f, 0.f};

    {
        if (tid < 128) CP16(smem_u32(&Ks[0][tid][0]), g_kb + ((size_t)(b * NN + kbase + tid)) * 8);
        #pragma unroll
        for (int i2 = 0; i2 < 4; i2++) {
            int idx = tid + i2 * 256, key = idx >> 3, c8 = (idx & 7) * 8;
            CP16(smem_u32(&Vs[0][key][c8]), g_v + ((size_t)(b * NN + kbase + key)) * CC + c8);
        }
        CP_COMMIT();
    }

    for (int t = 0; t < NTILE; t++) {
        if (t + 1 < NTILE) {
            int nb = (t + 1) & 1, k0 = kbase + (t + 1) * 128;
            if (tid < 128) CP16(smem_u32(&Ks[nb][tid][0]), g_kb + ((size_t)(b * NN + k0 + tid)) * 8);
            #pragma unroll
            for (int i2 = 0; i2 < 4; i2++) {
                int idx = tid + i2 * 256, key = idx >> 3, c8 = (idx & 7) * 8;
                CP16(smem_u32(&Vs[nb][key][c8]), g_v + ((size_t)(b * NN + k0 + key)) * CC + c8);
            }
            CP_COMMIT();
            asm volatile("cp.async.wait_group 1;" ::: "memory");
        } else {
            asm volatile("cp.async.wait_group 0;" ::: "memory");
        }
        __syncthreads();
        int bs = t & 1;

        uint32_t aK = smem_u32(&Ks[bs][lane & 15][0]);
        uint32_t aV = smem_u32(&Vs[bs][lane & 15][(lane >> 4) * 8]);
        #pragma unroll 2
        for (int kc = 0; kc < 8; kc++) {
            uint32_t kb0, kb1;
            asm volatile("ldmatrix.sync.aligned.m8n8.x2.shared.b16 {%0,%1}, [%2];"
                         : "=r"(kb0), "=r"(kb1) : "r"(aK));
            uint32_t vb[8][2];
            #pragma unroll
            for (int m = 0; m < 4; m++) {
                asm volatile("ldmatrix.sync.aligned.m8n8.x4.trans.shared.b16 {%0,%1,%2,%3}, [%4];"
                             : "=r"(vb[2 * m][0]), "=r"(vb[2 * m][1]),
                               "=r"(vb[2 * m + 1][0]), "=r"(vb[2 * m + 1][1])
                             : "r"(aV + m * 32));
            }
            aK += 16 * 16;        // 16 rows x 16 B
            aV += 16 * 144;       // 16 rows x 144 B
            float s0[4] = {0.f, 0.f, 0.f, 0.f}, s1[4] = {0.f, 0.f, 0.f, 0.f};
            MMA_BF16_K8(s0, qa0, qa1, kb0);
            MMA_BF16_K8(s1, qa0, qa1, kb1);
            uint32_t pa0, pa1, pa2, pa3;
            asm("cvt.rn.f16x2.f32 %0, %1, %2;" : "=r"(pa0) : "f"(s0[1]), "f"(s0[0]));
            asm("cvt.rn.f16x2.f32 %0, %1, %2;" : "=r"(pa1) : "f"(s0[3]), "f"(s0[2]));
            asm("cvt.rn.f16x2.f32 %0, %1, %2;" : "=r"(pa2) : "f"(s1[1]), "f"(s1[0]));
            asm("cvt.rn.f16x2.f32 %0, %1, %2;" : "=r"(pa3) : "f"(s1[3]), "f"(s1[2]));
            asm("ex2.approx.f16x2 %0, %0;" : "+r"(pa0));
            asm("ex2.approx.f16x2 %0, %0;" : "+r"(pa1));
            asm("ex2.approx.f16x2 %0, %0;" : "+r"(pa2));
            asm("ex2.approx.f16x2 %0, %0;" : "+r"(pa3));
            uint32_t h0, h1;
            asm("add.rn.f16x2 %0, %1, %2;" : "=r"(h0) : "r"(pa0), "r"(pa2));
            asm("add.rn.f16x2 %0, %1, %2;" : "=r"(h1) : "r"(pa1), "r"(pa3));
            float2 f0 = __half22float2(*reinterpret_cast<__half2*>(&h0));
            float2 f1 = __half22float2(*reinterpret_cast<__half2*>(&h1));
            lrow[0] += f0.x + f0.y;
            lrow[1] += f1.x + f1.y;
            #pragma unroll
            for (int j = 0; j < 8; j++)
                MMA_F16(d2[j], pa0, pa1, pa2, pa3, vb[j][0], vb[j][1]);
        }
        __syncthreads();
    }

    #pragma unroll
    for (int r = 0; r < 2; r++) {
        lrow[r] += __shfl_xor_sync(0xffffffffu, lrow[r], 1);
        lrow[r] += __shfl_xor_sync(0xffffffffu, lrow[r], 2);
    }
    int bs2 = b * KSPL + sp;
    int q0 = qbase + g, q1 = qbase + g + 8;
    if (tp == 0) {
        g_pl[(size_t)bs2 * NN + q0] = lrow[0];
        g_pl[(size_t)bs2 * NN + q1] = lrow[1];
    }
    float* pD = g_pD + (size_t)bs2 * CC * NN;
    #pragma unroll
    for (int j = 0; j < 8; j++) {
        int ch = j * 8 + 2 * tp;
        pD[(size_t)ch * NN + q0]       = d2[j][0];
        pD[(size_t)(ch + 1) * NN + q0] = d2[j][1];
        pD[(size_t)ch * NN + q1]       = d2[j][2];
        pD[(size_t)(ch + 1) * NN + q1] = d2[j][3];
    }
}

// ---------------- Stage D: combine splits + epilogue ----------------------------
__global__ void __launch_bounds__(256) k_comb(const float* __restrict__ gamma,
                                              const float* __restrict__ cnn,
                                              float* __restrict__ out) {
    int b = blockIdx.y;
    int q = blockIdx.x * 128 + (threadIdx.x & 127);
    int cg = (threadIdx.x >> 7) * 32;
    float l = g_pl[(size_t)(b * KSPL) * NN + q] + g_pl[(size_t)(b * KSPL + 1) * NN + q];
    float inv = gamma[0] / l;
    const float* p0 = g_pD + (size_t)(b * KSPL) * CC * NN + q;
    const float* p1 = g_pD + (size_t)(b * KSPL + 1) * CC * NN + q;
    const float* cb = cnn + (size_t)b * CC * NN + q;
    float* ob = out + (size_t)b * CC * NN + q;
    #pragma unroll 8
    for (int i = 0; i < 32; i++) {
        size_t off = (size_t)(cg + i) * NN;
        ob[off] = (p0[off] + p1[off]) * inv + cb[off];
    }
}

// ---------------- launch ---------------------------------------------------------
extern "C" void kernel_launch(void* const* d_in, const int* in_sizes, int n_in,
                              void* d_out, int out_size) {
    const float* cnn   = (const float*)d_in[0];
    const float* vit   = (const float*)d_in[1];
    const float* Wq    = (const float*)d_in[2];
    const float* bq    = (const float*)d_in[3];
    const float* Wk    = (const float*)d_in[4];
    const float* bk    = (const float*)d_in[5];
    const float* Wv    = (const float*)d_in[6];
    const float* bv    = (const float*)d_in[7];
    const float* gamma = (const float*)d_in[8];
    const float* gcnn  = (const float*)d_in[9];
    const float* gvit  = (const float*)d_in[10];
    float* out = (float*)d_out;

    k_gram <<<dim3(NCHUNK, NIMG), 256>>>(cnn, vit);
    k_prep <<<NIMG, 256>>>(Wq, Wk, Wv, gcnn, gvit);
    k_qkv  <<<dim3(NN / 32, BB), 192>>>(cnn, vit, bq, bk, bv);
    k_attn <<<dim3(NN / 128, BB, KSPL), 256>>>();
    k_comb <<<dim3(NN / 128, BB), 256>>>(gamma, cnn, out);
}

// round 8
// speedup vs baseline: 5.1175x; 1.0508x over previous
#include <cuda_runtime.h>
#include <cuda_bf16.h>
#include <cuda_fp16.h>
#include <cstdint>

// Problem constants
#define BB 4
#define CC 64
#define NN 4096
#define C8V 8
#define NIMG 8
#define NCHUNK 32
#define KSPL 4
#define NTILE (NN / KSPL / 128)
#define RLN2 1.4426950408889634f

// ---------------- scratch ----------------------------------------------------
__device__ float g_gpart[NCHUNK * NIMG * CC * CC];
__device__ float g_WqT[BB * CC * C8V];             // [b][c][o], prescaled by 1/ln2
__device__ float g_WkT[BB * CC * C8V];             // [b][c][o]
__device__ float g_WvTe[BB * CC * CC];             // [b][c][o]
__device__ __nv_bfloat16 g_qb[BB * NN * C8V];      // [b][n][8] (prescaled 1/ln2)
__device__ __nv_bfloat16 g_kb[BB * NN * C8V];      // [b][n][8]
__device__ __half        g_v [BB * NN * CC];       // [b][n][c]
__device__ float g_pD[BB * KSPL * CC * NN];        // attention partial D [b][s][c][q]
__device__ float g_pl[BB * KSPL * NN];             // attention partial l [b][s][q]

__device__ __forceinline__ uint32_t smem_u32(const void* p) {
    uint32_t a;
    asm("{ .reg .u64 t; cvta.to.shared.u64 t, %1; cvt.u32.u64 %0, t; }" : "=r"(a) : "l"(p));
    return a;
}

#define MMA_BF16_K8(d, a0, a1, b0)                                                 \
    asm volatile("mma.sync.aligned.m16n8k8.row.col.f32.bf16.bf16.f32 "             \
        "{%0,%1,%2,%3}, {%4,%5}, {%6}, {%0,%1,%2,%3};"                             \
        : "+f"((d)[0]), "+f"((d)[1]), "+f"((d)[2]), "+f"((d)[3])                   \
        : "r"(a0), "r"(a1), "r"(b0))

#define MMA_F16(d, a0, a1, a2, a3, b0, b1)                                         \
    asm volatile("mma.sync.aligned.m16n8k16.row.col.f32.f16.f16.f32 "              \
        "{%0,%1,%2,%3}, {%4,%5,%6,%7}, {%8,%9}, {%0,%1,%2,%3};"                    \
        : "+f"((d)[0]), "+f"((d)[1]), "+f"((d)[2]), "+f"((d)[3])                   \
        : "r"(a0), "r"(a1), "r"(a2), "r"(a3), "r"(b0), "r"(b1))

#define CP16(dst, src) asm volatile("cp.async.cg.shared.global [%0], [%1], 16;" :: "r"(dst), "l"(src) : "memory")
#define CP_COMMIT()    asm volatile("cp.async.commit_group;" ::: "memory")

// ---------------- Stage A1: gram partials (4x4 register tiles) -----------------
__global__ void k_gram(const float* __restrict__ cnn, const float* __restrict__ vit) {
    int chunk = blockIdx.x, img = blockIdx.y;
    const float* x = (img < BB) ? (cnn + img * CC * NN) : (vit + (img - BB) * CC * NN);
    __shared__ float xs[CC][132];
    int n0 = chunk * 128;
    for (int i = threadIdx.x; i < CC * 128; i += 256) {
        int c = i >> 7, j = i & 127;
        xs[c][j] = x[c * NN + n0 + j];
    }
    __syncthreads();
    int tx = threadIdx.x & 15, ty = threadIdx.x >> 4;
    int ci0 = ty * 4, cj0 = tx * 4;
    float acc[4][4];
    #pragma unroll
    for (int i = 0; i < 4; i++)
        #pragma unroll
        for (int j = 0; j < 4; j++) acc[i][j] = 0.f;
    for (int j = 0; j < 128; j += 4) {
        float4 a[4], bvv[4];
        #pragma unroll
        for (int i = 0; i < 4; i++) a[i] = *(const float4*)&xs[ci0 + i][j];
        #pragma unroll
        for (int i = 0; i < 4; i++) bvv[i] = *(const float4*)&xs[cj0 + i][j];
        #pragma unroll
        for (int i = 0; i < 4; i++)
            #pragma unroll
            for (int jj = 0; jj < 4; jj++)
                acc[i][jj] += a[i].x * bvv[jj].x + a[i].y * bvv[jj].y
                            + a[i].z * bvv[jj].z + a[i].w * bvv[jj].w;
    }
    float* outp = g_gpart + (chunk * NIMG + img) * CC * CC;
    #pragma unroll
    for (int i = 0; i < 4; i++)
        *(float4*)&outp[(ci0 + i) * CC + cj0] =
            make_float4(acc[i][0], acc[i][1], acc[i][2], acc[i][3]);
}

// ---------------- Stage A2: reduce + softmax + effective-weight compose --------
__global__ void k_prep(const float* __restrict__ Wq, const float* __restrict__ Wk,
                       const float* __restrict__ Wv,
                       const float* __restrict__ gcnn, const float* __restrict__ gvit) {
    int img = blockIdx.x;
    int tid = threadIdx.x;
    __shared__ __align__(16) float As[CC * CC];
    __shared__ __align__(16) float Wvs[CC * 68];
    __shared__ float Wqs[CC * C8V];

    for (int p = tid; p < CC * CC; p += 256) {
        float s = 0.f;
        #pragma unroll
        for (int ch = 0; ch < NCHUNK; ch++)
            s += g_gpart[(ch * NIMG + img) * CC * CC + p];
        As[p] = s;
    }
    __syncthreads();

    {
        int r = tid >> 2, l4 = tid & 3;
        float m = -1e30f;
        for (int d = l4; d < CC; d += 4) m = fmaxf(m, -As[r * CC + d]);
        m = fmaxf(m, __shfl_xor_sync(0xffffffffu, m, 1));
        m = fmaxf(m, __shfl_xor_sync(0xffffffffu, m, 2));
        float s = 0.f;
        for (int d = l4; d < CC; d += 4) s += __expf(-As[r * CC + d] - m);
        s += __shfl_xor_sync(0xffffffffu, s, 1);
        s += __shfl_xor_sync(0xffffffffu, s, 2);
        float inv = 1.f / s;
        for (int d = l4; d < CC; d += 4)
            As[r * CC + d] = __expf(-As[r * CC + d] - m) * inv;
    }

    const float* Wsm = (img < BB) ? Wq : Wk;
    for (int i = tid; i < C8V * CC; i += 256)
        Wqs[(i & 63) * C8V + (i >> 6)] = Wsm[i];
    if (img >= BB) {
        for (int i = tid; i < CC * CC; i += 256)
            Wvs[(i & 63) * 68 + (i >> 6)] = Wv[i];
    }
    __syncthreads();

    if (img < BB) {
        float g = gcnn[0];
        for (int p = tid; p < CC * C8V; p += 256) {
            int d = p >> 3, o = p & 7;
            float s = 0.f;
            #pragma unroll 4
            for (int c = 0; c < CC; c++) s += Wqs[c * C8V + o] * As[c * CC + d];
            g_WqT[img * CC * C8V + d * C8V + o] = (Wqs[d * C8V + o] + g * s) * RLN2;
        }
    } else {
        int b = img - BB;
        float g = gvit[0];
        for (int p = tid; p < CC * C8V; p += 256) {
            int d = p >> 3, o = p & 7;
            float s = 0.f;
            #pragma unroll 4
            for (int c = 0; c < CC; c++) s += Wqs[c * C8V + o] * As[c * CC + d];
            g_WkT[b * CC * C8V + d * C8V + o] = Wqs[d * C8V + o] + g * s;
        }
        int tx = tid & 15, ty = tid >> 4;
        int o0 = tx * 4, d0 = ty * 4;
        float acc[4][4];
        #pragma unroll
        for (int i = 0; i < 4; i++)
            #pragma unroll
            for (int j = 0; j < 4; j++) acc[i][j] = 0.f;
        for (int c = 0; c < CC; c++) {
            float4 a = *(const float4*)&As[c * CC + d0];
            float4 wv = *(const float4*)&Wvs[c * 68 + o0];
            float ar[4] = {a.x, a.y, a.z, a.w};
            float wr[4] = {wv.x, wv.y, wv.z, wv.w};
            #pragma unroll
            for (int i = 0; i < 4; i++)
                #pragma unroll
                for (int j = 0; j < 4; j++) acc[i][j] += ar[i] * wr[j];
        }
        #pragma unroll
        for (int i = 0; i < 4; i++) {
            float4 wd = *(const float4*)&Wvs[(d0 + i) * 68 + o0];
            float4 o = make_float4(wd.x + g * acc[i][0], wd.y + g * acc[i][1],
                                   wd.z + g * acc[i][2], wd.w + g * acc[i][3]);
            *(float4*)&g_WvTe[b * CC * CC + (d0 + i) * CC + o0] = o;
        }
    }
}

// ---------------- Stage B: fused q/k/v projections ------------------------------
__global__ void __launch_bounds__(192) k_qkv(const float* __restrict__ cnn,
                                             const float* __restrict__ vit,
                                             const float* __restrict__ bq,
                                             const float* __restrict__ bk,
                                             const float* __restrict__ bv) {
    int n0 = blockIdx.x * 32, b = blockIdx.y;
    int tid = threadIdx.x, ww = tid >> 5, lane = tid & 31;
    int n = n0 + lane;

    __shared__ __align__(16) float Wvs[CC * CC];
    __shared__ __align__(16) float Wqs[CC * C8V];
    __shared__ __align__(16) float Wks[CC * C8V];

    const float* wsrc = g_WvTe + b * CC * CC;
    for (int i = tid; i < CC * CC / 4; i += 192)
        *(float4*)&Wvs[i * 4] = *(const float4*)&wsrc[i * 4];
    if (tid < 128) {
        *(float4*)&Wqs[tid * 4] = *(const float4*)&g_WqT[b * CC * C8V + tid * 4];
        *(float4*)&Wks[tid * 4] = *(const float4*)&g_WkT[b * CC * C8V + tid * 4];
    }
    __syncthreads();

    if (ww < 4) {
        int og = ww * 16;
        const float* src = vit + (size_t)b * CC * NN;
        float acc[16];
        #pragma unroll
        for (int i = 0; i < 16; i++) acc[i] = bv[og + i];
        #pragma unroll 4
        for (int c = 0; c < CC; c++) {
            float xv = src[c * NN + n];
            #pragma unroll
            for (int m = 0; m < 4; m++) {
                float4 w = *(const float4*)&Wvs[c * CC + og + m * 4];
                acc[m * 4 + 0] += w.x * xv; acc[m * 4 + 1] += w.y * xv;
                acc[m * 4 + 2] += w.z * xv; acc[m * 4 + 3] += w.w * xv;
            }
        }
        __half* dst = g_v + ((size_t)(b * NN + n)) * CC + og;
        #pragma unroll
        for (int m = 0; m < 4; m++) {
            ushort4 u;
            u.x = __half_as_ushort(__float2half(acc[m * 4 + 0]));
            u.y = __half_as_ushort(__float2half(acc[m * 4 + 1]));
            u.z = __half_as_ushort(__float2half(acc[m * 4 + 2]));
            u.w = __half_as_ushort(__float2half(acc[m * 4 + 3]));
            *(ushort4*)(dst + m * 4) = u;
        }
    } else {
        bool isQ = (ww == 4);
        const float* src = (isQ ? cnn : vit) + (size_t)b * CC * NN;
        const float* Ws = isQ ? Wqs : Wks;
        const float* bias = isQ ? bq : bk;
        float bscale = isQ ? RLN2 : 1.0f;
        __nv_bfloat16* dst = isQ ? g_qb : g_kb;
        float acc[8];
        #pragma unroll
        for (int o = 0; o < 8; o++) acc[o] = bias[o] * bscale;
        #pragma unroll 8
        for (int c = 0; c < CC; c++) {
            float xv = src[c * NN + n];
            float4 w0 = *(const float4*)&Ws[c * C8V];
            float4 w1 = *(const float4*)&Ws[c * C8V + 4];
            acc[0] += w0.x * xv; acc[1] += w0.y * xv; acc[2] += w0.z * xv; acc[3] += w0.w * xv;
            acc[4] += w1.x * xv; acc[5] += w1.y * xv; acc[6] += w1.z * xv; acc[7] += w1.w * xv;
        }
        ushort4 u0, u1;
        u0.x = __bfloat16_as_ushort(__float2bfloat16(acc[0]));
        u0.y = __bfloat16_as_ushort(__float2bfloat16(acc[1]));
        u0.z = __bfloat16_as_ushort(__float2bfloat16(acc[2]));
        u0.w = __bfloat16_as_ushort(__float2bfloat16(acc[3]));
        u1.x = __bfloat16_as_ushort(__float2bfloat16(acc[4]));
        u1.y = __bfloat16_as_ushort(__float2bfloat16(acc[5]));
        u1.z = __bfloat16_as_ushort(__float2bfloat16(acc[6]));
        u1.w = __bfloat16_as_ushort(__float2bfloat16(acc[7]));
        *(ushort4*)(dst + ((size_t)(b * NN + n)) * 8)     = u0;
        *(ushort4*)(dst + ((size_t)(b * NN + n)) * 8 + 4) = u1;
    }
}

// ---------------- Stage C: mma attention --------------------------------------
// grid (16, 4, 4), 256 threads (8 warps x 32 q rows = 256 q rows/CTA).
// Ones-column in V smem accumulates row-sums via an extra MMA (j = 8).
__global__ void __launch_bounds__(256, 2) k_attn() {
    int qt = blockIdx.x, b = blockIdx.y, sp = blockIdx.z;
    int tid = threadIdx.x;
    int w = tid >> 5, lane = tid & 31;
    int g = lane >> 2, tp = lane & 3;
    int kbase = sp * (NN / KSPL);

    __shared__ __align__(16) __nv_bfloat16 Ks[2][128][8];
    __shared__ __align__(16) __half        Vs[2][128][72];

    // init ones columns (cols 64..71: [64]=1.0, rest 0); never overwritten by cp.async
    for (int i = tid; i < 2 * 128; i += 256) {
        uint4 z; z.x = 0x00003C00u; z.y = 0; z.z = 0; z.w = 0;
        *(uint4*)&Vs[i >> 7][i & 127][64] = z;
    }
    __syncthreads();

    // constant B fragment for the ones block (same for every kc / tile)
    uint32_t vbO0, vbO1;
    asm volatile("ldmatrix.sync.aligned.m8n8.x2.trans.shared.b16 {%0,%1}, [%2];"
                 : "=r"(vbO0), "=r"(vbO1) : "r"(smem_u32(&Vs[0][lane & 15][64])));

    int qrow = qt * 256 + w * 32;
    uint32_t qa[2][2];
    #pragma unroll
    for (int i = 0; i < 2; i++) {
        qa[i][0] = *(const uint32_t*)(g_qb + ((size_t)(b * NN + qrow + i * 16 + g)) * 8 + 2 * tp);
        qa[i][1] = *(const uint32_t*)(g_qb + ((size_t)(b * NN + qrow + i * 16 + g + 8)) * 8 + 2 * tp);
    }

    float d2[2][9][4];
    #pragma unroll
    for (int i = 0; i < 2; i++)
        #pragma unroll
        for (int j = 0; j < 9; j++)
            #pragma unroll
            for (int r = 0; r < 4; r++) d2[i][j][r] = 0.f;

    {
        if (tid < 128) CP16(smem_u32(&Ks[0][tid][0]), g_kb + ((size_t)(b * NN + kbase + tid)) * 8);
        #pragma unroll
        for (int i2 = 0; i2 < 4; i2++) {
            int idx = tid + i2 * 256, key = idx >> 3, c8 = (idx & 7) * 8;
            CP16(smem_u32(&Vs[0][key][c8]), g_v + ((size_t)(b * NN + kbase + key)) * CC + c8);
        }
        CP_COMMIT();
    }

    for (int t = 0; t < NTILE; t++) {
        if (t + 1 < NTILE) {
            int nb = (t + 1) & 1, k0 = kbase + (t + 1) * 128;
            if (tid < 128) CP16(smem_u32(&Ks[nb][tid][0]), g_kb + ((size_t)(b * NN + k0 + tid)) * 8);
            #pragma unroll
            for (int i2 = 0; i2 < 4; i2++) {
                int idx = tid + i2 * 256, key = idx >> 3, c8 = (idx & 7) * 8;
                CP16(smem_u32(&Vs[nb][key][c8]), g_v + ((size_t)(b * NN + k0 + key)) * CC + c8);
            }
            CP_COMMIT();
            asm volatile("cp.async.wait_group 1;" ::: "memory");
        } else {
            asm volatile("cp.async.wait_group 0;" ::: "memory");
        }
        __syncthreads();
        int bs = t & 1;

        uint32_t aK = smem_u32(&Ks[bs][lane & 15][0]);
        uint32_t aV = smem_u32(&Vs[bs][lane & 15][(lane >> 4) * 8]);
        #pragma unroll 2
        for (int kc = 0; kc < 8; kc++) {
            uint32_t kb0, kb1;
            asm volatile("ldmatrix.sync.aligned.m8n8.x2.shared.b16 {%0,%1}, [%2];"
                         : "=r"(kb0), "=r"(kb1) : "r"(aK));
            uint32_t vb[8][2];
            #pragma unroll
            for (int m = 0; m < 4; m++) {
                asm volatile("ldmatrix.sync.aligned.m8n8.x4.trans.shared.b16 {%0,%1,%2,%3}, [%4];"
                             : "=r"(vb[2 * m][0]), "=r"(vb[2 * m][1]),
                               "=r"(vb[2 * m + 1][0]), "=r"(vb[2 * m + 1][1])
                             : "r"(aV + m * 32));
            }
            aK += 16 * 16;
            aV += 16 * 144;
            #pragma unroll
            for (int i = 0; i < 2; i++) {
                float s0[4] = {0.f, 0.f, 0.f, 0.f}, s1[4] = {0.f, 0.f, 0.f, 0.f};
                MMA_BF16_K8(s0, qa[i][0], qa[i][1], kb0);
                MMA_BF16_K8(s1, qa[i][0], qa[i][1], kb1);
                uint32_t pa0, pa1, pa2, pa3;
                asm("cvt.rn.f16x2.f32 %0, %1, %2;" : "=r"(pa0) : "f"(s0[1]), "f"(s0[0]));
                asm("cvt.rn.f16x2.f32 %0, %1, %2;" : "=r"(pa1) : "f"(s0[3]), "f"(s0[2]));
                asm("cvt.rn.f16x2.f32 %0, %1, %2;" : "=r"(pa2) : "f"(s1[1]), "f"(s1[0]));
                asm("cvt.rn.f16x2.f32 %0, %1, %2;" : "=r"(pa3) : "f"(s1[3]), "f"(s1[2]));
                asm("ex2.approx.f16x2 %0, %0;" : "+r"(pa0));
                asm("ex2.approx.f16x2 %0, %0;" : "+r"(pa1));
                asm("ex2.approx.f16x2 %0, %0;" : "+r"(pa2));
                asm("ex2.approx.f16x2 %0, %0;" : "+r"(pa3));
                #pragma unroll
                for (int j = 0; j < 8; j++)
                    MMA_F16(d2[i][j], pa0, pa1, pa2, pa3, vb[j][0], vb[j][1]);
                MMA_F16(d2[i][8], pa0, pa1, pa2, pa3, vbO0, vbO1);
            }
        }
        __syncthreads();
    }

    // store partials (l lives in d2[i][8][0]/[2] on tp==0 threads: V column 64)
    int bs2 = b * KSPL + sp;
    float* pD = g_pD + (size_t)bs2 * CC * NN;
    #pragma unroll
    for (int i = 0; i < 2; i++) {
        int q0 = qrow + i * 16 + g, q1 = q0 + 8;
        if (tp == 0) {
            g_pl[(size_t)bs2 * NN + q0] = d2[i][8][0];
            g_pl[(size_t)bs2 * NN + q1] = d2[i][8][2];
        }
        #pragma unroll
        for (int j = 0; j < 8; j++) {
            int ch = j * 8 + 2 * tp;
            pD[(size_t)ch * NN + q0]       = d2[i][j][0];
            pD[(size_t)(ch + 1) * NN + q0] = d2[i][j][1];
            pD[(size_t)ch * NN + q1]       = d2[i][j][2];
            pD[(size_t)(ch + 1) * NN + q1] = d2[i][j][3];
        }
    }
}

// ---------------- Stage D: combine splits + epilogue ----------------------------
__global__ void __launch_bounds__(256) k_comb(const float* __restrict__ gamma,
                                              const float* __restrict__ cnn,
                                              float* __restrict__ out) {
    int b = blockIdx.y;
    int q = blockIdx.x * 128 + (threadIdx.x & 127);
    int cg = (threadIdx.x >> 7) * 32;
    float l = 0.f;
    #pragma unroll
    for (int s = 0; s < KSPL; s++) l += g_pl[(size_t)(b * KSPL + s) * NN + q];
    float inv = gamma[0] / l;
    const float* p0 = g_pD + (size_t)(b * KSPL + 0) * CC * NN + q;
    const float* p1 = g_pD + (size_t)(b * KSPL + 1) * CC * NN + q;
    const float* p2 = g_pD + (size_t)(b * KSPL + 2) * CC * NN + q;
    const float* p3 = g_pD + (size_t)(b * KSPL + 3) * CC * NN + q;
    const float* cb = cnn + (size_t)b * CC * NN + q;
    float* ob = out + (size_t)b * CC * NN + q;
    #pragma unroll 8
    for (int i = 0; i < 32; i++) {
        size_t off = (size_t)(cg + i) * NN;
        ob[off] = ((p0[off] + p1[off]) + (p2[off] + p3[off])) * inv + cb[off];
    }
}

// ---------------- launch ---------------------------------------------------------
extern "C" void kernel_launch(void* const* d_in, const int* in_sizes, int n_in,
                              void* d_out, int out_size) {
    const float* cnn   = (const float*)d_in[0];
    const float* vit   = (const float*)d_in[1];
    const float* Wq    = (const float*)d_in[2];
    const float* bq    = (const float*)d_in[3];
    const float* Wk    = (const float*)d_in[4];
    const float* bk    = (const float*)d_in[5];
    const float* Wv    = (const float*)d_in[6];
    const float* bv    = (const float*)d_in[7];
    const float* gamma = (const float*)d_in[8];
    const float* gcnn  = (const float*)d_in[9];
    const float* gvit  = (const float*)d_in[10];
    float* out = (float*)d_out;

    k_gram <<<dim3(NCHUNK, NIMG), 256>>>(cnn, vit);
    k_prep <<<NIMG, 256>>>(Wq, Wk, Wv, gcnn, gvit);
    k_qkv  <<<dim3(NN / 32, BB), 192>>>(cnn, vit, bq, bk, bv);
    k_attn <<<dim3(NN / 256, BB, KSPL), 256>>>();
    k_comb <<<dim3(NN / 128, BB), 256>>>(gamma, cnn, out);
}